// round 1
// baseline (speedup 1.0000x reference)
#include <cuda_runtime.h>
#include <math.h>

// Problem constants
#define T_SEQ 1024
#define EMB   1024
#define NH    16
#define HD    64
#define BATCH 8
#define M_ROWS 8192          // B*T
#define NREL  2047           // 2*T - 1

// ---------------- scratch (device globals; no allocation allowed) ----------
__device__ float g_q[8388608];      // [B,H,T,D] 32MB
__device__ float g_k[8388608];
__device__ float g_v[8388608];
__device__ float g_o[8388608];      // [B,T,E]  32MB
__device__ float g_bias[NREL * NH]; // effective interpolated bias table

// ---------------- kernel 1: fold offset interpolation into bias table ------
__global__ void bias_kernel(const float* __restrict__ table,
                            const float* __restrict__ offset,
                            float* __restrict__ out) {
    int idx = blockIdx.x * 256 + threadIdx.x;
    if (idx >= NREL * NH) return;
    int r = idx / NH, h = idx % NH;
    float bounded = tanhf(offset[0]) * 0.5f;
    float adj = fminf(fmaxf((float)r + bounded, 0.0f), 2046.0f);
    float lof = floorf(adj);
    int lo = (int)lof;
    int hi = (int)ceilf(adj);
    float w = adj - lof;
    out[idx] = table[lo * NH + h] * (1.0f - w) + table[hi * NH + h] * w;
}

// ---------------- kernel 2: C[m,n] = sum_k X[m,k] * W[n,k] + bias[n] -------
// M=8192, N=K=1024 hardcoded. layout==0: out[m,n] row-major.
// layout==1: out written as [B,H,T,D]  (b=m>>10, t=m&1023, h=n>>6, d=n&63)
__global__ void __launch_bounds__(256, 2) gemm_xwT(
    const float* __restrict__ X, const float* __restrict__ W,
    const float* __restrict__ bias, float* __restrict__ out, int layout)
{
    __shared__ float As[16][136];
    __shared__ float Bs[16][136];
    const int K = 1024;
    int bm = blockIdx.y * 128;
    int bn = blockIdx.x * 128;
    int tid = threadIdx.x;
    int tx = tid & 15, ty = tid >> 4;

    float acc[8][8];
    #pragma unroll
    for (int i = 0; i < 8; i++)
        #pragma unroll
        for (int j = 0; j < 8; j++) acc[i][j] = 0.0f;

    for (int kt = 0; kt < K; kt += 16) {
        // load 128x16 tiles of X and W (transposed into smem: [k][row])
        #pragma unroll
        for (int i = 0; i < 2; i++) {
            int lin = tid + i * 256;          // 0..511
            int row = lin >> 2;               // 0..127
            int kq  = (lin & 3) << 2;         // 0,4,8,12
            float4 a = *(const float4*)&X[(size_t)(bm + row) * K + kt + kq];
            As[kq + 0][row] = a.x; As[kq + 1][row] = a.y;
            As[kq + 2][row] = a.z; As[kq + 3][row] = a.w;
            float4 b = *(const float4*)&W[(size_t)(bn + row) * K + kt + kq];
            Bs[kq + 0][row] = b.x; Bs[kq + 1][row] = b.y;
            Bs[kq + 2][row] = b.z; Bs[kq + 3][row] = b.w;
        }
        __syncthreads();
        #pragma unroll
        for (int kk = 0; kk < 16; kk++) {
            float a[8], b[8];
            *(float4*)&a[0] = *(float4*)&As[kk][ty * 8];
            *(float4*)&a[4] = *(float4*)&As[kk][ty * 8 + 4];
            // cols: {tx*4 .. tx*4+3} and {64+tx*4 .. 64+tx*4+3}
            *(float4*)&b[0] = *(float4*)&Bs[kk][tx * 4];
            *(float4*)&b[4] = *(float4*)&Bs[kk][64 + tx * 4];
            #pragma unroll
            for (int i = 0; i < 8; i++)
                #pragma unroll
                for (int j = 0; j < 8; j++)
                    acc[i][j] += a[i] * b[j];
        }
        __syncthreads();
    }

    #pragma unroll
    for (int i = 0; i < 8; i++) {
        int m = bm + ty * 8 + i;
        #pragma unroll
        for (int g = 0; g < 2; g++) {
            int n = bn + g * 64 + tx * 4;
            float4 bv = *(const float4*)&bias[n];
            float4 o;
            o.x = acc[i][g * 4 + 0] + bv.x;
            o.y = acc[i][g * 4 + 1] + bv.y;
            o.z = acc[i][g * 4 + 2] + bv.z;
            o.w = acc[i][g * 4 + 3] + bv.w;
            if (layout == 0) {
                *(float4*)&out[(size_t)m * 1024 + n] = o;
            } else {
                int b = m >> 10, t = m & 1023, h = n >> 6, d = n & 63;
                *(float4*)&out[(((size_t)b * NH + h) * T_SEQ + t) * HD + d] = o;
            }
        }
    }
}

// ---------------- kernel 3: flash attention, fp32 --------------------------
// grid (T/64, B*H); block 256. Q,K,V in [B,H,T,D]; O written as [B,T,E].
__global__ void __launch_bounds__(256, 2) attn_kernel(
    const float* __restrict__ Qg, const float* __restrict__ Kg,
    const float* __restrict__ Vg, const float* __restrict__ biasEff,
    float* __restrict__ Og)
{
    extern __shared__ float sm[];
    float* Qs    = sm;               // 64 x 68
    float* Ks    = sm + 4352;        // 64 x 68
    float* Vs    = sm + 2 * 4352;    // 64 x 68
    float* Ps    = sm + 3 * 4352;    // 64 x 68
    float* sbias = sm + 4 * 4352;    // 128

    int bh = blockIdx.y;             // b*NH + h
    int h  = bh & (NH - 1);
    int q0 = blockIdx.x * 64;
    int tid = threadIdx.x;
    int tx = tid & 15, ty = tid >> 4;

    const float* Qbase = Qg + (size_t)bh * T_SEQ * HD + (size_t)q0 * HD;

    // load Q tile [64 x 64]
    #pragma unroll
    for (int i = 0; i < 4; i++) {
        int lin = tid + i * 256;
        int r = lin >> 4, c4 = (lin & 15) * 4;
        *(float4*)&Qs[r * 68 + c4] = *(const float4*)&Qbase[r * HD + c4];
    }

    float m_run[4], l_run[4], acc[4][4];
    #pragma unroll
    for (int i = 0; i < 4; i++) {
        m_run[i] = -1e30f; l_run[i] = 0.0f;
        #pragma unroll
        for (int j = 0; j < 4; j++) acc[i][j] = 0.0f;
    }
    const float scale = 0.125f;  // 1/sqrt(64)

    for (int kt = 0; kt < T_SEQ; kt += 64) {
        const float* Kbase = Kg + (size_t)bh * T_SEQ * HD + (size_t)kt * HD;
        const float* Vbase = Vg + (size_t)bh * T_SEQ * HD + (size_t)kt * HD;
        #pragma unroll
        for (int i = 0; i < 4; i++) {
            int lin = tid + i * 256;
            int r = lin >> 4, c4 = (lin & 15) * 4;
            *(float4*)&Ks[r * 68 + c4] = *(const float4*)&Kbase[r * HD + c4];
            *(float4*)&Vs[r * 68 + c4] = *(const float4*)&Vbase[r * HD + c4];
        }
        // bias slice: rel = (q-k)+1023, rel_min = q0-kt+960, 127 entries
        if (tid < 127) {
            int relmin = q0 - kt + 960;
            sbias[tid] = biasEff[(relmin + tid) * NH + h];
        }
        __syncthreads();

        // S = Q K^T  (thread cols: tx + 16*jj to keep K reads 2-way max)
        float s[4][4];
        #pragma unroll
        for (int i = 0; i < 4; i++)
            #pragma unroll
            for (int j = 0; j < 4; j++) s[i][j] = 0.0f;

        #pragma unroll 4
        for (int d = 0; d < 64; d += 4) {
            float4 qv[4], kv[4];
            #pragma unroll
            for (int i = 0; i < 4; i++)
                qv[i] = *(float4*)&Qs[(ty * 4 + i) * 68 + d];
            #pragma unroll
            for (int j = 0; j < 4; j++)
                kv[j] = *(float4*)&Ks[(tx + 16 * j) * 68 + d];
            #pragma unroll
            for (int i = 0; i < 4; i++)
                #pragma unroll
                for (int j = 0; j < 4; j++)
                    s[i][j] += qv[i].x * kv[j].x + qv[i].y * kv[j].y
                             + qv[i].z * kv[j].z + qv[i].w * kv[j].w;
        }
        // scale + bias
        #pragma unroll
        for (int i = 0; i < 4; i++)
            #pragma unroll
            for (int j = 0; j < 4; j++)
                s[i][j] = s[i][j] * scale
                        + sbias[(ty * 4 + i) - (tx + 16 * j) + 63];

        // online softmax over rows (16 lanes share a row)
        #pragma unroll
        for (int i = 0; i < 4; i++) {
            float mx = fmaxf(fmaxf(s[i][0], s[i][1]), fmaxf(s[i][2], s[i][3]));
            #pragma unroll
            for (int off = 8; off > 0; off >>= 1)
                mx = fmaxf(mx, __shfl_xor_sync(0xffffffffu, mx, off, 16));
            float mn = fmaxf(m_run[i], mx);
            float corr = __expf(m_run[i] - mn);
            m_run[i] = mn;
            float ls = 0.0f;
            #pragma unroll
            for (int j = 0; j < 4; j++) {
                s[i][j] = __expf(s[i][j] - mn);
                ls += s[i][j];
            }
            #pragma unroll
            for (int off = 8; off > 0; off >>= 1)
                ls += __shfl_xor_sync(0xffffffffu, ls, off, 16);
            l_run[i] = l_run[i] * corr + ls;
            #pragma unroll
            for (int j = 0; j < 4; j++) acc[i][j] *= corr;
        }

        // write P (scalar stores, lanes contiguous -> conflict-free)
        #pragma unroll
        for (int i = 0; i < 4; i++)
            #pragma unroll
            for (int j = 0; j < 4; j++)
                Ps[(ty * 4 + i) * 68 + tx + 16 * j] = s[i][j];
        __syncwarp();

        // O += P V   (thread d-cols: tx*4 .. tx*4+3)
        #pragma unroll 4
        for (int k = 0; k < 64; k += 4) {
            float4 pv[4];
            #pragma unroll
            for (int i = 0; i < 4; i++)
                pv[i] = *(float4*)&Ps[(ty * 4 + i) * 68 + k];
            #pragma unroll
            for (int kk = 0; kk < 4; kk++) {
                float4 vv = *(float4*)&Vs[(k + kk) * 68 + tx * 4];
                #pragma unroll
                for (int i = 0; i < 4; i++) {
                    float p = (kk == 0) ? pv[i].x : (kk == 1) ? pv[i].y
                            : (kk == 2) ? pv[i].z : pv[i].w;
                    acc[i][0] += p * vv.x; acc[i][1] += p * vv.y;
                    acc[i][2] += p * vv.z; acc[i][3] += p * vv.w;
                }
            }
        }
        __syncthreads();
    }

    // epilogue: normalize and write O as [B,T,E]
    int b = bh >> 4;
    #pragma unroll
    for (int i = 0; i < 4; i++) {
        float inv = 1.0f / l_run[i];
        int t = q0 + ty * 4 + i;
        float4 o;
        o.x = acc[i][0] * inv; o.y = acc[i][1] * inv;
        o.z = acc[i][2] * inv; o.w = acc[i][3] * inv;
        *(float4*)&Og[((size_t)b * T_SEQ + t) * EMB + h * HD + tx * 4] = o;
    }
}

// ---------------- launch ----------------------------------------------------
extern "C" void kernel_launch(void* const* d_in, const int* in_sizes, int n_in,
                              void* d_out, int out_size) {
    const float* query = (const float*)d_in[0];
    const float* key_  = (const float*)d_in[1];
    const float* value = (const float*)d_in[2];
    const float* Wq = (const float*)d_in[3];
    const float* bq = (const float*)d_in[4];
    const float* Wk = (const float*)d_in[5];
    const float* bk = (const float*)d_in[6];
    const float* Wv = (const float*)d_in[7];
    const float* bv = (const float*)d_in[8];
    const float* Wo = (const float*)d_in[9];
    const float* bo = (const float*)d_in[10];
    const float* bias_table = (const float*)d_in[11];
    const float* offset     = (const float*)d_in[12];
    float* out = (float*)d_out;

    void *pq, *pk, *pv, *po, *pb;
    cudaGetSymbolAddress(&pq, g_q);
    cudaGetSymbolAddress(&pk, g_k);
    cudaGetSymbolAddress(&pv, g_v);
    cudaGetSymbolAddress(&po, g_o);
    cudaGetSymbolAddress(&pb, g_bias);

    bias_kernel<<<(NREL * NH + 255) / 256, 256>>>(bias_table, offset, (float*)pb);

    dim3 ggrid(8, 64);   // N/128, M/128
    gemm_xwT<<<ggrid, 256>>>(query, Wq, bq, (float*)pq, 1);
    gemm_xwT<<<ggrid, 256>>>(key_,  Wk, bk, (float*)pk, 1);
    gemm_xwT<<<ggrid, 256>>>(value, Wv, bv, (float*)pv, 1);

    const int ATTN_SMEM = (4 * 64 * 68 + 128) * 4;  // 70144 bytes
    cudaFuncSetAttribute(attn_kernel,
                         cudaFuncAttributeMaxDynamicSharedMemorySize, ATTN_SMEM);
    attn_kernel<<<dim3(T_SEQ / 64, BATCH * NH), 256, ATTN_SMEM>>>(
        (const float*)pq, (const float*)pk, (const float*)pv,
        (const float*)pb, (float*)po);

    gemm_xwT<<<ggrid, 256>>>((const float*)po, Wo, bo, out, 0);
}

// round 6
// speedup vs baseline: 1.5082x; 1.5082x over previous
#include <cuda_runtime.h>
#include <cuda_fp16.h>
#include <cstdint>
#include <math.h>

#define T_SEQ 1024
#define EMB   1024
#define NH    16
#define HD    64
#define BATCH 8
#define NREL  2047
#define K3    3072          // tripled K for fp16 hi/lo split GEMM
#define KCH   48            // K3 / 64
#define NSTG  4             // pipeline stages

// ---------------- scratch (device globals) ----------------------------------
__device__ __align__(16) float g_q[8388608];        // [B*T, E] fp32
__device__ __align__(16) float g_k[8388608];
__device__ __align__(16) float g_v[8388608];
__device__ __align__(16) float g_o[8388608];
__device__ __align__(16) float g_bias[NREL * NH];
__device__ __align__(16) __half g_a3[25165824];     // [8192, 3072] fp16
__device__ __align__(16) __half g_w3[3145728];      // [1024, 3072] fp16

// ---------------- PTX helpers ------------------------------------------------
__device__ __forceinline__ uint32_t smem_u32(const void* p) {
    uint32_t a;
    asm("{ .reg .u64 t; cvta.to.shared.u64 t, %1; cvt.u32.u64 %0, t; }"
        : "=r"(a) : "l"(p));
    return a;
}

#define CP_ASYNC16(dst, src) \
    asm volatile("cp.async.cg.shared.global [%0], [%1], 16;" :: "r"(dst), "l"(src))
#define CP_COMMIT() asm volatile("cp.async.commit_group;" ::: "memory")
#define CP_WAIT2()  asm volatile("cp.async.wait_group 2;" ::: "memory")

#define LDSM_X4(r0, r1, r2, r3, addr) \
    asm volatile("ldmatrix.sync.aligned.m8n8.x4.shared.b16 {%0,%1,%2,%3}, [%4];" \
        : "=r"(r0), "=r"(r1), "=r"(r2), "=r"(r3) : "r"(addr))

#define MMA16816(d, a0, a1, a2, a3, b0, b1) \
    asm volatile("mma.sync.aligned.m16n8k16.row.col.f32.f16.f16.f32 " \
        "{%0,%1,%2,%3},{%4,%5,%6,%7},{%8,%9},{%0,%1,%2,%3};" \
        : "+f"((d)[0]), "+f"((d)[1]), "+f"((d)[2]), "+f"((d)[3]) \
        : "r"(a0), "r"(a1), "r"(a2), "r"(a3), "r"(b0), "r"(b1))

// ---------------- kernel 1: bias interpolation ------------------------------
__global__ void bias_kernel(const float* __restrict__ table,
                            const float* __restrict__ offset,
                            float* __restrict__ out) {
    int idx = blockIdx.x * 256 + threadIdx.x;
    if (idx >= NREL * NH) return;
    int r = idx / NH, h = idx % NH;
    float bounded = tanhf(offset[0]) * 0.5f;
    float adj = fminf(fmaxf((float)r + bounded, 0.0f), 2046.0f);
    float lof = floorf(adj);
    int lo = (int)lof;
    int hi = (int)ceilf(adj);
    float w = adj - lof;
    out[idx] = table[lo * NH + h] * (1.0f - w) + table[hi * NH + h] * w;
}

// ---------------- kernel 2: fp32 -> fp16 hi/lo split, K-tripled --------------
// mode 0 (activations): blocks [hi, hi, lo];  mode 1 (weights): [hi, lo, hi]
__global__ void convert3(const float* __restrict__ in, __half* __restrict__ out,
                         int rows, int mode) {
    size_t idx = ((size_t)blockIdx.x * 256 + threadIdx.x) * 4;
    if (idx >= (size_t)rows * 1024) return;
    size_t row = idx >> 10;
    int col = (int)(idx & 1023);
    float4 x = *(const float4*)&in[idx];
    __half h0 = __float2half_rn(x.x), h1 = __float2half_rn(x.y);
    __half h2 = __float2half_rn(x.z), h3 = __float2half_rn(x.w);
    __half l0 = __float2half_rn(x.x - __half2float(h0));
    __half l1 = __float2half_rn(x.y - __half2float(h1));
    __half l2 = __float2half_rn(x.z - __half2float(h2));
    __half l3 = __float2half_rn(x.w - __half2float(h3));
    __half2 hA, hB, lA, lB;
    hA.x = h0; hA.y = h1; hB.x = h2; hB.y = h3;
    lA.x = l0; lA.y = l1; lB.x = l2; lB.y = l3;
    __half2* o0 = (__half2*)&out[row * K3 + col];
    __half2* o1 = (__half2*)&out[row * K3 + 1024 + col];
    __half2* o2 = (__half2*)&out[row * K3 + 2048 + col];
    o0[0] = hA; o0[1] = hB;
    if (mode == 0) { o1[0] = hA; o1[1] = hB; o2[0] = lA; o2[1] = lB; }
    else           { o1[0] = lA; o1[1] = lB; o2[0] = hA; o2[1] = hB; }
}

// ---------------- kernel 3: mma.sync fp16 GEMM, C = A3 * W3^T + bias --------
// A3: [8192, 3072], W3: [1024, 3072] fp16; out fp32 row-major [8192, 1024].
// CTA tile 128x128, warp tile 64x32, K stage 64, 4-stage cp.async pipeline.
// smem per stage: A 128 rows x 144B + B 128 rows x 144B = 36864 B.
#define ST_A   18432
#define ST_SZ  36864
__global__ void __launch_bounds__(256, 1)
gemm_tc(const __half* __restrict__ A, const __half* __restrict__ Bm,
        const float* __restrict__ bias, float* __restrict__ out)
{
    extern __shared__ __align__(128) char smem[];
    uint32_t sbase = smem_u32(smem);

    int tid = threadIdx.x;
    int wid = tid >> 5, lid = tid & 31;
    int wm = wid >> 2, wn = wid & 3;           // 2 x 4 warp grid
    size_t bm = (size_t)blockIdx.y * 128;
    size_t bn = (size_t)blockIdx.x * 128;

    const __half* gA = A + bm * K3;
    const __half* gB = Bm + bn * K3;

    // per-thread cp.async source/dest (4 A chunks + 4 B chunks per stage)
    int ldrow = tid >> 3;          // 0..31  (x4 rows via +32 stride)
    int ldch  = tid & 7;           // 16B chunk within 128B row

    // prologue: stages 0..2
    #pragma unroll
    for (int s = 0; s < NSTG - 1; s++) {
        uint32_t st = sbase + s * ST_SZ;
        #pragma unroll
        for (int i = 0; i < 4; i++) {
            int row = ldrow + i * 32;
            CP_ASYNC16(st + row * 144 + ldch * 16,
                       gA + (size_t)row * K3 + s * 64 + ldch * 8);
            CP_ASYNC16(st + ST_A + row * 144 + ldch * 16,
                       gB + (size_t)row * K3 + s * 64 + ldch * 8);
        }
        CP_COMMIT();
    }

    float acc[4][4][4];
    #pragma unroll
    for (int mi = 0; mi < 4; mi++)
        #pragma unroll
        for (int ni = 0; ni < 4; ni++)
            #pragma unroll
            for (int e = 0; e < 4; e++) acc[mi][ni][e] = 0.0f;

    // per-lane ldmatrix offsets (bytes) within a stage
    uint32_t aOff = (uint32_t)((wm * 64 + (lid & 15)) * 144 + (lid >> 4) * 16);
    uint32_t bOff = (uint32_t)(ST_A +
        (wn * 32 + (lid & 7) + ((lid >> 4) << 3)) * 144 + ((lid >> 3) & 1) * 16);

    for (int c = 0; c < KCH; c++) {
        CP_WAIT2();
        __syncthreads();

        // issue stage c+3
        if (c + NSTG - 1 < KCH) {
            int cc = c + NSTG - 1;
            uint32_t st = sbase + (cc & 3) * ST_SZ;
            #pragma unroll
            for (int i = 0; i < 4; i++) {
                int row = ldrow + i * 32;
                CP_ASYNC16(st + row * 144 + ldch * 16,
                           gA + (size_t)row * K3 + cc * 64 + ldch * 8);
                CP_ASYNC16(st + ST_A + row * 144 + ldch * 16,
                           gB + (size_t)row * K3 + cc * 64 + ldch * 8);
            }
        }
        CP_COMMIT();

        // compute stage c
        uint32_t st = sbase + (c & 3) * ST_SZ;
        #pragma unroll
        for (int kk = 0; kk < 4; kk++) {
            uint32_t a[4][4], b[2][4];
            #pragma unroll
            for (int mi = 0; mi < 4; mi++)
                LDSM_X4(a[mi][0], a[mi][1], a[mi][2], a[mi][3],
                        st + aOff + mi * (16 * 144) + kk * 32);
            #pragma unroll
            for (int j = 0; j < 2; j++)
                LDSM_X4(b[j][0], b[j][1], b[j][2], b[j][3],
                        st + bOff + j * (16 * 144) + kk * 32);
            #pragma unroll
            for (int mi = 0; mi < 4; mi++)
                #pragma unroll
                for (int ni = 0; ni < 4; ni++)
                    MMA16816(acc[mi][ni],
                             a[mi][0], a[mi][1], a[mi][2], a[mi][3],
                             b[ni >> 1][(ni & 1) * 2], b[ni >> 1][(ni & 1) * 2 + 1]);
        }
    }

    // epilogue: bias + store (C fragment: d0,d1 at (t/4, t%4*2), d2,d3 at +8 rows)
    #pragma unroll
    for (int mi = 0; mi < 4; mi++) {
        size_t r0 = bm + wm * 64 + mi * 16 + (lid >> 2);
        #pragma unroll
        for (int ni = 0; ni < 4; ni++) {
            size_t col = bn + wn * 32 + ni * 8 + (lid & 3) * 2;
            float2 bv = *(const float2*)&bias[col];
            float2 o0, o1;
            o0.x = acc[mi][ni][0] + bv.x; o0.y = acc[mi][ni][1] + bv.y;
            o1.x = acc[mi][ni][2] + bv.x; o1.y = acc[mi][ni][3] + bv.y;
            *(float2*)&out[r0 * 1024 + col] = o0;
            *(float2*)&out[(r0 + 8) * 1024 + col] = o1;
        }
    }
}

// ---------------- kernel 4: flash attention, fp32 ----------------------------
// Q,K,V row-major [B*T, E]; head h -> cols h*64..h*64+63. O -> [B,T,E].
__global__ void __launch_bounds__(256, 2) attn_kernel(
    const float* __restrict__ Qg, const float* __restrict__ Kg,
    const float* __restrict__ Vg, const float* __restrict__ biasEff,
    float* __restrict__ Og)
{
    extern __shared__ float sm[];
    float* Qs    = sm;
    float* Ks    = sm + 4352;
    float* Vs    = sm + 2 * 4352;
    float* Ps    = sm + 3 * 4352;
    float* sbias = sm + 4 * 4352;

    int bh = blockIdx.y;
    int h  = bh & (NH - 1);
    int b  = bh >> 4;
    int q0 = blockIdx.x * 64;
    int tid = threadIdx.x;
    int tx = tid & 15, ty = tid >> 4;

    const float* Qbase = Qg + ((size_t)b * T_SEQ + q0) * EMB + h * HD;

    #pragma unroll
    for (int i = 0; i < 4; i++) {
        int lin = tid + i * 256;
        int r = lin >> 4, c4 = (lin & 15) * 4;
        *(float4*)&Qs[r * 68 + c4] = *(const float4*)&Qbase[(size_t)r * EMB + c4];
    }

    float m_run[4], l_run[4], acc[4][4];
    #pragma unroll
    for (int i = 0; i < 4; i++) {
        m_run[i] = -1e30f; l_run[i] = 0.0f;
        #pragma unroll
        for (int j = 0; j < 4; j++) acc[i][j] = 0.0f;
    }
    const float scale = 0.125f;

    for (int kt = 0; kt < T_SEQ; kt += 64) {
        const float* Kbase = Kg + ((size_t)b * T_SEQ + kt) * EMB + h * HD;
        const float* Vbase = Vg + ((size_t)b * T_SEQ + kt) * EMB + h * HD;
        #pragma unroll
        for (int i = 0; i < 4; i++) {
            int lin = tid + i * 256;
            int r = lin >> 4, c4 = (lin & 15) * 4;
            *(float4*)&Ks[r * 68 + c4] = *(const float4*)&Kbase[(size_t)r * EMB + c4];
            *(float4*)&Vs[r * 68 + c4] = *(const float4*)&Vbase[(size_t)r * EMB + c4];
        }
        if (tid < 127) {
            int relmin = q0 - kt + 960;
            sbias[tid] = biasEff[(relmin + tid) * NH + h];
        }
        __syncthreads();

        float s[4][4];
        #pragma unroll
        for (int i = 0; i < 4; i++)
            #pragma unroll
            for (int j = 0; j < 4; j++) s[i][j] = 0.0f;

        #pragma unroll 4
        for (int d = 0; d < 64; d += 4) {
            float4 qv[4], kv[4];
            #pragma unroll
            for (int i = 0; i < 4; i++)
                qv[i] = *(float4*)&Qs[(ty * 4 + i) * 68 + d];
            #pragma unroll
            for (int j = 0; j < 4; j++)
                kv[j] = *(float4*)&Ks[(tx + 16 * j) * 68 + d];
            #pragma unroll
            for (int i = 0; i < 4; i++)
                #pragma unroll
                for (int j = 0; j < 4; j++)
                    s[i][j] += qv[i].x * kv[j].x + qv[i].y * kv[j].y
                             + qv[i].z * kv[j].z + qv[i].w * kv[j].w;
        }
        #pragma unroll
        for (int i = 0; i < 4; i++)
            #pragma unroll
            for (int j = 0; j < 4; j++)
                s[i][j] = s[i][j] * scale
                        + sbias[(ty * 4 + i) - (tx + 16 * j) + 63];

        #pragma unroll
        for (int i = 0; i < 4; i++) {
            float mx = fmaxf(fmaxf(s[i][0], s[i][1]), fmaxf(s[i][2], s[i][3]));
            #pragma unroll
            for (int off = 8; off > 0; off >>= 1)
                mx = fmaxf(mx, __shfl_xor_sync(0xffffffffu, mx, off, 16));
            float mn = fmaxf(m_run[i], mx);
            float corr = __expf(m_run[i] - mn);
            m_run[i] = mn;
            float ls = 0.0f;
            #pragma unroll
            for (int j = 0; j < 4; j++) {
                s[i][j] = __expf(s[i][j] - mn);
                ls += s[i][j];
            }
            #pragma unroll
            for (int off = 8; off > 0; off >>= 1)
                ls += __shfl_xor_sync(0xffffffffu, ls, off, 16);
            l_run[i] = l_run[i] * corr + ls;
            #pragma unroll
            for (int j = 0; j < 4; j++) acc[i][j] *= corr;
        }

        #pragma unroll
        for (int i = 0; i < 4; i++)
            #pragma unroll
            for (int j = 0; j < 4; j++)
                Ps[(ty * 4 + i) * 68 + tx + 16 * j] = s[i][j];
        __syncwarp();

        #pragma unroll 4
        for (int k = 0; k < 64; k += 4) {
            float4 pv[4];
            #pragma unroll
            for (int i = 0; i < 4; i++)
                pv[i] = *(float4*)&Ps[(ty * 4 + i) * 68 + k];
            #pragma unroll
            for (int kk = 0; kk < 4; kk++) {
                float4 vv = *(float4*)&Vs[(k + kk) * 68 + tx * 4];
                #pragma unroll
                for (int i = 0; i < 4; i++) {
                    float p = (kk == 0) ? pv[i].x : (kk == 1) ? pv[i].y
                            : (kk == 2) ? pv[i].z : pv[i].w;
                    acc[i][0] += p * vv.x; acc[i][1] += p * vv.y;
                    acc[i][2] += p * vv.z; acc[i][3] += p * vv.w;
                }
            }
        }
        __syncthreads();
    }

    #pragma unroll
    for (int i = 0; i < 4; i++) {
        float inv = 1.0f / l_run[i];
        int t = q0 + ty * 4 + i;
        float4 o;
        o.x = acc[i][0] * inv; o.y = acc[i][1] * inv;
        o.z = acc[i][2] * inv; o.w = acc[i][3] * inv;
        *(float4*)&Og[((size_t)b * T_SEQ + t) * EMB + h * HD + tx * 4] = o;
    }
}

// ---------------- launch -----------------------------------------------------
extern "C" void kernel_launch(void* const* d_in, const int* in_sizes, int n_in,
                              void* d_out, int out_size) {
    const float* query = (const float*)d_in[0];
    const float* key_  = (const float*)d_in[1];
    const float* value = (const float*)d_in[2];
    const float* Wq = (const float*)d_in[3];
    const float* bq = (const float*)d_in[4];
    const float* Wk = (const float*)d_in[5];
    const float* bk = (const float*)d_in[6];
    const float* Wv = (const float*)d_in[7];
    const float* bv = (const float*)d_in[8];
    const float* Wo = (const float*)d_in[9];
    const float* bo = (const float*)d_in[10];
    const float* bias_table = (const float*)d_in[11];
    const float* offset     = (const float*)d_in[12];
    float* out = (float*)d_out;

    void *pq, *pk, *pv, *po, *pb, *pa3, *pw3;
    cudaGetSymbolAddress(&pq, g_q);
    cudaGetSymbolAddress(&pk, g_k);
    cudaGetSymbolAddress(&pv, g_v);
    cudaGetSymbolAddress(&po, g_o);
    cudaGetSymbolAddress(&pb, g_bias);
    cudaGetSymbolAddress(&pa3, g_a3);
    cudaGetSymbolAddress(&pw3, g_w3);
    __half* a3 = (__half*)pa3;
    __half* w3 = (__half*)pw3;

    const int GEMM_SMEM = NSTG * ST_SZ;      // 147456
    cudaFuncSetAttribute(gemm_tc, cudaFuncAttributeMaxDynamicSharedMemorySize, GEMM_SMEM);
    const int ATTN_SMEM = (4 * 64 * 68 + 128) * 4;
    cudaFuncSetAttribute(attn_kernel, cudaFuncAttributeMaxDynamicSharedMemorySize, ATTN_SMEM);

    dim3 ggrid(8, 64);   // N/128, M/128

    bias_kernel<<<(NREL * NH + 255) / 256, 256>>>(bias_table, offset, (float*)pb);

    // Q projection
    convert3<<<8192, 256>>>(query, a3, 8192, 0);
    convert3<<<1024, 256>>>(Wq, w3, 1024, 1);
    gemm_tc<<<ggrid, 256, GEMM_SMEM>>>(a3, w3, bq, (float*)pq);
    // K projection
    convert3<<<8192, 256>>>(key_, a3, 8192, 0);
    convert3<<<1024, 256>>>(Wk, w3, 1024, 1);
    gemm_tc<<<ggrid, 256, GEMM_SMEM>>>(a3, w3, bk, (float*)pk);
    // V projection
    convert3<<<8192, 256>>>(value, a3, 8192, 0);
    convert3<<<1024, 256>>>(Wv, w3, 1024, 1);
    gemm_tc<<<ggrid, 256, GEMM_SMEM>>>(a3, w3, bv, (float*)pv);

    // attention
    attn_kernel<<<dim3(T_SEQ / 64, BATCH * NH), 256, ATTN_SMEM>>>(
        (const float*)pq, (const float*)pk, (const float*)pv,
        (const float*)pb, (float*)po);

    // output projection
    convert3<<<8192, 256>>>((const float*)po, a3, 8192, 0);
    convert3<<<1024, 256>>>(Wo, w3, 1024, 1);
    gemm_tc<<<ggrid, 256, GEMM_SMEM>>>(a3, w3, bo, out);
}

// round 7
// speedup vs baseline: 2.9242x; 1.9388x over previous
#include <cuda_runtime.h>
#include <cuda_fp16.h>
#include <cstdint>
#include <math.h>

#define T_SEQ 1024
#define EMB   1024
#define NH    16
#define HD    64
#define BATCH 8
#define NREL  2047
#define K3    3072
#define KCH   48
#define NSTG  3

// ---------------- scratch (device globals) ----------------------------------
__device__ __align__(16) float g_q[8388608];
__device__ __align__(16) float g_k[8388608];
__device__ __align__(16) float g_v[8388608];
__device__ __align__(16) float g_o[8388608];
__device__ __align__(16) float g_bias[NREL * NH];      // [h][rel]
__device__ __align__(16) __half g_a3[25165824];
__device__ __align__(16) __half g_w3[3145728];
__device__ __align__(16) __half g_q16[8388608];        // [bh][t][d]
__device__ __align__(16) __half g_k16[8388608];        // [bh][t][d]
__device__ __align__(16) __half g_v16t[8388608];       // [bh][d][t]

// ---------------- PTX helpers ------------------------------------------------
__device__ __forceinline__ uint32_t smem_u32(const void* p) {
    uint32_t a;
    asm("{ .reg .u64 t; cvta.to.shared.u64 t, %1; cvt.u32.u64 %0, t; }"
        : "=r"(a) : "l"(p));
    return a;
}

#define CP_ASYNC16(dst, src) \
    asm volatile("cp.async.cg.shared.global [%0], [%1], 16;" :: "r"(dst), "l"(src))
#define CP_COMMIT() asm volatile("cp.async.commit_group;" ::: "memory")
#define CP_WAIT1()  asm volatile("cp.async.wait_group 1;" ::: "memory")
#define CP_WAIT0()  asm volatile("cp.async.wait_group 0;" ::: "memory")

#define LDSM_X4(r0, r1, r2, r3, addr) \
    asm volatile("ldmatrix.sync.aligned.m8n8.x4.shared.b16 {%0,%1,%2,%3}, [%4];" \
        : "=r"(r0), "=r"(r1), "=r"(r2), "=r"(r3) : "r"(addr))

#define MMA16816(d, a0, a1, a2, a3, b0, b1) \
    asm volatile("mma.sync.aligned.m16n8k16.row.col.f32.f16.f16.f32 " \
        "{%0,%1,%2,%3},{%4,%5,%6,%7},{%8,%9},{%0,%1,%2,%3};" \
        : "+f"((d)[0]), "+f"((d)[1]), "+f"((d)[2]), "+f"((d)[3]) \
        : "r"(a0), "r"(a1), "r"(a2), "r"(a3), "r"(b0), "r"(b1))

__device__ __forceinline__ uint32_t pack_h2(float a, float b) {
    __half2 h = __float22half2_rn(make_float2(a, b));
    return *reinterpret_cast<uint32_t*>(&h);
}

// ---------------- kernel 1: bias interpolation -> [h][rel] ------------------
__global__ void bias_kernel(const float* __restrict__ table,
                            const float* __restrict__ offset,
                            float* __restrict__ out) {
    int idx = blockIdx.x * 256 + threadIdx.x;
    if (idx >= NREL * NH) return;
    int r = idx / NH, h = idx % NH;
    float bounded = tanhf(offset[0]) * 0.5f;
    float adj = fminf(fmaxf((float)r + bounded, 0.0f), 2046.0f);
    float lof = floorf(adj);
    int lo = (int)lof;
    int hi = (int)ceilf(adj);
    float w = adj - lof;
    out[h * NREL + r] = table[lo * NH + h] * (1.0f - w) + table[hi * NH + h] * w;
}

// ---------------- kernel 2: fp32 -> fp16 hi/lo split, K-tripled --------------
__global__ void convert3(const float* __restrict__ in, __half* __restrict__ out,
                         int rows, int mode) {
    size_t idx = ((size_t)blockIdx.x * 256 + threadIdx.x) * 4;
    if (idx >= (size_t)rows * 1024) return;
    size_t row = idx >> 10;
    int col = (int)(idx & 1023);
    float4 x = *(const float4*)&in[idx];
    __half h0 = __float2half_rn(x.x), h1 = __float2half_rn(x.y);
    __half h2 = __float2half_rn(x.z), h3 = __float2half_rn(x.w);
    __half l0 = __float2half_rn(x.x - __half2float(h0));
    __half l1 = __float2half_rn(x.y - __half2float(h1));
    __half l2 = __float2half_rn(x.z - __half2float(h2));
    __half l3 = __float2half_rn(x.w - __half2float(h3));
    __half2 hA, hB, lA, lB;
    hA.x = h0; hA.y = h1; hB.x = h2; hB.y = h3;
    lA.x = l0; lA.y = l1; lB.x = l2; lB.y = l3;
    __half2* o0 = (__half2*)&out[row * K3 + col];
    __half2* o1 = (__half2*)&out[row * K3 + 1024 + col];
    __half2* o2 = (__half2*)&out[row * K3 + 2048 + col];
    o0[0] = hA; o0[1] = hB;
    if (mode == 0) { o1[0] = hA; o1[1] = hB; o2[0] = lA; o2[1] = lB; }
    else           { o1[0] = lA; o1[1] = lB; o2[0] = hA; o2[1] = hB; }
}

// ---------------- kernel 2b: fp32 [B*T,E] -> fp16 [bh][t][d] ----------------
__global__ void conv16(const float* __restrict__ in, __half* __restrict__ out) {
    size_t idx = ((size_t)blockIdx.x * 256 + threadIdx.x) * 4;
    size_t m = idx >> 10;
    int e = (int)(idx & 1023);
    int b = (int)(m >> 10), t = (int)(m & 1023);
    int h = e >> 6, d = e & 63;
    float4 x = *(const float4*)&in[idx];
    __half2 p0 = __float22half2_rn(make_float2(x.x, x.y));
    __half2 p1 = __float22half2_rn(make_float2(x.z, x.w));
    __half2* dst = (__half2*)&out[(((size_t)b * NH + h) * T_SEQ + t) * HD + d];
    dst[0] = p0; dst[1] = p1;
}

// ---------------- kernel 2c: fp32 [B*T,E] -> fp16 [bh][d][t] (V transposed) -
__global__ void conv16t(const float* __restrict__ in, __half* __restrict__ out) {
    size_t lin = (size_t)blockIdx.x * 256 + threadIdx.x;   // 2,097,152 total
    int d = (int)(lin & 63);
    size_t rest = lin >> 6;
    int h = (int)(rest & 15); rest >>= 4;
    int t4 = (int)(rest & 255);
    int b = (int)(rest >> 8);
    int t0 = t4 * 4;
    float v0 = in[((size_t)b * T_SEQ + t0 + 0) * EMB + h * HD + d];
    float v1 = in[((size_t)b * T_SEQ + t0 + 1) * EMB + h * HD + d];
    float v2 = in[((size_t)b * T_SEQ + t0 + 2) * EMB + h * HD + d];
    float v3 = in[((size_t)b * T_SEQ + t0 + 3) * EMB + h * HD + d];
    __half2 p0 = __float22half2_rn(make_float2(v0, v1));
    __half2 p1 = __float22half2_rn(make_float2(v2, v3));
    __half2* dst = (__half2*)&out[(((size_t)b * NH + h) * HD + d) * T_SEQ + t0];
    dst[0] = p0; dst[1] = p1;
}

// ---------------- kernel 3: mma.sync fp16 GEMM, 3-stage, occ 2 --------------
#define ST_A   18432
#define ST_SZ  36864
__global__ void __launch_bounds__(256, 2)
gemm_tc(const __half* __restrict__ A, const __half* __restrict__ Bm,
        const float* __restrict__ bias, float* __restrict__ out)
{
    extern __shared__ __align__(128) char smem[];
    uint32_t sbase = smem_u32(smem);

    int tid = threadIdx.x;
    int wid = tid >> 5, lid = tid & 31;
    int wm = wid >> 2, wn = wid & 3;
    size_t bm = (size_t)blockIdx.y * 128;
    size_t bn = (size_t)blockIdx.x * 128;

    const __half* gA = A + bm * K3;
    const __half* gB = Bm + bn * K3;

    int ldrow = tid >> 3;
    int ldch  = tid & 7;

    #pragma unroll
    for (int s = 0; s < NSTG - 1; s++) {
        uint32_t st = sbase + s * ST_SZ;
        #pragma unroll
        for (int i = 0; i < 4; i++) {
            int row = ldrow + i * 32;
            CP_ASYNC16(st + row * 144 + ldch * 16,
                       gA + (size_t)row * K3 + s * 64 + ldch * 8);
            CP_ASYNC16(st + ST_A + row * 144 + ldch * 16,
                       gB + (size_t)row * K3 + s * 64 + ldch * 8);
        }
        CP_COMMIT();
    }

    float acc[4][4][4];
    #pragma unroll
    for (int mi = 0; mi < 4; mi++)
        #pragma unroll
        for (int ni = 0; ni < 4; ni++)
            #pragma unroll
            for (int e = 0; e < 4; e++) acc[mi][ni][e] = 0.0f;

    uint32_t aOff = (uint32_t)((wm * 64 + (lid & 15)) * 144 + (lid >> 4) * 16);
    uint32_t bOff = (uint32_t)(ST_A +
        (wn * 32 + (lid & 7) + ((lid >> 4) << 3)) * 144 + ((lid >> 3) & 1) * 16);

    int cs = 0, ls = NSTG - 1;
    for (int c = 0; c < KCH; c++) {
        CP_WAIT1();
        __syncthreads();

        if (c + NSTG - 1 < KCH) {
            int cc = c + NSTG - 1;
            uint32_t st = sbase + ls * ST_SZ;
            #pragma unroll
            for (int i = 0; i < 4; i++) {
                int row = ldrow + i * 32;
                CP_ASYNC16(st + row * 144 + ldch * 16,
                           gA + (size_t)row * K3 + cc * 64 + ldch * 8);
                CP_ASYNC16(st + ST_A + row * 144 + ldch * 16,
                           gB + (size_t)row * K3 + cc * 64 + ldch * 8);
            }
        }
        CP_COMMIT();

        uint32_t st = sbase + cs * ST_SZ;
        #pragma unroll
        for (int kk = 0; kk < 4; kk++) {
            uint32_t a[4][4], b[2][4];
            #pragma unroll
            for (int mi = 0; mi < 4; mi++)
                LDSM_X4(a[mi][0], a[mi][1], a[mi][2], a[mi][3],
                        st + aOff + mi * (16 * 144) + kk * 32);
            #pragma unroll
            for (int j = 0; j < 2; j++)
                LDSM_X4(b[j][0], b[j][1], b[j][2], b[j][3],
                        st + bOff + j * (16 * 144) + kk * 32);
            #pragma unroll
            for (int mi = 0; mi < 4; mi++)
                #pragma unroll
                for (int ni = 0; ni < 4; ni++)
                    MMA16816(acc[mi][ni],
                             a[mi][0], a[mi][1], a[mi][2], a[mi][3],
                             b[ni >> 1][(ni & 1) * 2], b[ni >> 1][(ni & 1) * 2 + 1]);
        }
        cs = (cs == NSTG - 1) ? 0 : cs + 1;
        ls = (ls == NSTG - 1) ? 0 : ls + 1;
    }

    #pragma unroll
    for (int mi = 0; mi < 4; mi++) {
        size_t r0 = bm + wm * 64 + mi * 16 + (lid >> 2);
        #pragma unroll
        for (int ni = 0; ni < 4; ni++) {
            size_t col = bn + wn * 32 + ni * 8 + (lid & 3) * 2;
            float2 bv = *(const float2*)&bias[col];
            float2 o0, o1;
            o0.x = acc[mi][ni][0] + bv.x; o0.y = acc[mi][ni][1] + bv.y;
            o1.x = acc[mi][ni][2] + bv.x; o1.y = acc[mi][ni][3] + bv.y;
            *(float2*)&out[r0 * 1024 + col] = o0;
            *(float2*)&out[(r0 + 8) * 1024 + col] = o1;
        }
    }
}

// ---------------- kernel 4: fp16 mma flash attention -------------------------
// grid (8, 128): q-tile 128 per CTA, one (b,h) per blockIdx.y. 8 warps x 16 rows.
// K-tile 64 keys, double-buffered cp.async. O -> g_o [B,T,E] fp32.
#define A_SQ   0
#define A_SK   18432
#define A_SV   36864
#define A_SB   55296
#define A_SMEM 59904
__global__ void __launch_bounds__(256)
attn_mma(const __half* __restrict__ Q16, const __half* __restrict__ K16,
         const __half* __restrict__ V16t, const float* __restrict__ biasT,
         float* __restrict__ Og)
{
    extern __shared__ __align__(128) char smem[];
    uint32_t sbase = smem_u32(smem);
    float* sbias = (float*)(smem + A_SB);

    int bh = blockIdx.y;
    int h = bh & (NH - 1), b = bh >> 4;
    int q0 = blockIdx.x * 128;
    int tid = threadIdx.x;
    int w = tid >> 5, lid = tid & 31;

    const __half* gQ = Q16 + ((size_t)bh * T_SEQ + q0) * HD;
    const __half* gK = K16 + (size_t)bh * T_SEQ * HD;
    const __half* gV = V16t + (size_t)bh * HD * T_SEQ;

    // prologue: Q tile (128x64) + K/V tile 0 in one group
    {
        #pragma unroll
        for (int i = 0; i < 4; i++) {
            int id = tid + i * 256;
            int row = id >> 3, ch = id & 7;
            CP_ASYNC16(sbase + A_SQ + row * 144 + ch * 16,
                       gQ + (size_t)row * HD + ch * 8);
        }
        #pragma unroll
        for (int i = 0; i < 2; i++) {
            int id = tid + i * 256;
            int row = id >> 3, ch = id & 7;
            CP_ASYNC16(sbase + A_SK + row * 144 + ch * 16,
                       gK + (size_t)row * HD + ch * 8);
            CP_ASYNC16(sbase + A_SV + row * 144 + ch * 16,
                       gV + (size_t)row * T_SEQ + ch * 8);
        }
        CP_COMMIT();
    }
    for (int j = tid; j < 1151; j += 256)
        sbias[j] = biasT[h * NREL + q0 + j];

    float o[8][4];
    #pragma unroll
    for (int i = 0; i < 8; i++)
        #pragma unroll
        for (int e = 0; e < 4; e++) o[i][e] = 0.0f;
    float m0 = -1e30f, m1 = -1e30f, l0 = 0.0f, l1 = 0.0f;
    uint32_t qa[4][4];

    int r0loc = w * 16 + (lid >> 2);

    for (int it = 0; it < 16; it++) {
        CP_WAIT0();
        __syncthreads();

        // issue next K/V tile into alternate buffer
        if (it < 15) {
            int kt2 = (it + 1) * 64;
            uint32_t bo = ((it + 1) & 1) * 9216;
            #pragma unroll
            for (int i = 0; i < 2; i++) {
                int id = tid + i * 256;
                int row = id >> 3, ch = id & 7;
                CP_ASYNC16(sbase + A_SK + bo + row * 144 + ch * 16,
                           gK + (size_t)(kt2 + row) * HD + ch * 8);
                CP_ASYNC16(sbase + A_SV + bo + row * 144 + ch * 16,
                           gV + (size_t)row * T_SEQ + kt2 + ch * 8);
            }
        }
        CP_COMMIT();

        if (it == 0) {
            #pragma unroll
            for (int kk = 0; kk < 4; kk++)
                LDSM_X4(qa[kk][0], qa[kk][1], qa[kk][2], qa[kk][3],
                        sbase + A_SQ + (w * 16 + (lid & 15)) * 144
                        + (lid >> 4) * 16 + kk * 32);
        }

        uint32_t kb = sbase + A_SK + (it & 1) * 9216;
        uint32_t vb = sbase + A_SV + (it & 1) * 9216;

        // S = Q K^T  (16 rows x 64 keys per warp)
        float s[8][4];
        #pragma unroll
        for (int i = 0; i < 8; i++)
            #pragma unroll
            for (int e = 0; e < 4; e++) s[i][e] = 0.0f;
        #pragma unroll
        for (int kk = 0; kk < 4; kk++) {
            #pragma unroll
            for (int nb = 0; nb < 4; nb++) {
                uint32_t bb[4];
                LDSM_X4(bb[0], bb[1], bb[2], bb[3],
                        kb + (nb * 16 + (lid & 7) + ((lid >> 4) << 3)) * 144
                        + ((lid >> 3) & 1) * 16 + kk * 32);
                MMA16816(s[nb * 2], qa[kk][0], qa[kk][1], qa[kk][2], qa[kk][3],
                         bb[0], bb[1]);
                MMA16816(s[nb * 2 + 1], qa[kk][0], qa[kk][1], qa[kk][2], qa[kk][3],
                         bb[2], bb[3]);
            }
        }

        // scale + bias
        int kcol = it * 64 + (lid & 3) * 2;
        #pragma unroll
        for (int nt = 0; nt < 8; nt++) {
            int jb = r0loc + 1023 - (kcol + nt * 8);
            s[nt][0] = s[nt][0] * 0.125f + sbias[jb];
            s[nt][1] = s[nt][1] * 0.125f + sbias[jb - 1];
            s[nt][2] = s[nt][2] * 0.125f + sbias[jb + 8];
            s[nt][3] = s[nt][3] * 0.125f + sbias[jb + 7];
        }

        // online softmax (rows r0loc and r0loc+8)
        float mx0 = -1e30f, mx1 = -1e30f;
        #pragma unroll
        for (int nt = 0; nt < 8; nt++) {
            mx0 = fmaxf(mx0, fmaxf(s[nt][0], s[nt][1]));
            mx1 = fmaxf(mx1, fmaxf(s[nt][2], s[nt][3]));
        }
        mx0 = fmaxf(mx0, __shfl_xor_sync(0xffffffffu, mx0, 1, 4));
        mx0 = fmaxf(mx0, __shfl_xor_sync(0xffffffffu, mx0, 2, 4));
        mx1 = fmaxf(mx1, __shfl_xor_sync(0xffffffffu, mx1, 1, 4));
        mx1 = fmaxf(mx1, __shfl_xor_sync(0xffffffffu, mx1, 2, 4));
        float mn0 = fmaxf(m0, mx0), mn1 = fmaxf(m1, mx1);
        float c0 = __expf(m0 - mn0), c1 = __expf(m1 - mn1);
        m0 = mn0; m1 = mn1;
        float ls0 = 0.0f, ls1 = 0.0f;
        #pragma unroll
        for (int nt = 0; nt < 8; nt++) {
            s[nt][0] = __expf(s[nt][0] - mn0); ls0 += s[nt][0];
            s[nt][1] = __expf(s[nt][1] - mn0); ls0 += s[nt][1];
            s[nt][2] = __expf(s[nt][2] - mn1); ls1 += s[nt][2];
            s[nt][3] = __expf(s[nt][3] - mn1); ls1 += s[nt][3];
        }
        l0 = l0 * c0 + ls0;
        l1 = l1 * c1 + ls1;
        #pragma unroll
        for (int dn = 0; dn < 8; dn++) {
            o[dn][0] *= c0; o[dn][1] *= c0;
            o[dn][2] *= c1; o[dn][3] *= c1;
        }

        // P fragments from S (register reuse)
        uint32_t ap[4][4];
        #pragma unroll
        for (int kk = 0; kk < 4; kk++) {
            ap[kk][0] = pack_h2(s[2 * kk][0], s[2 * kk][1]);
            ap[kk][1] = pack_h2(s[2 * kk][2], s[2 * kk][3]);
            ap[kk][2] = pack_h2(s[2 * kk + 1][0], s[2 * kk + 1][1]);
            ap[kk][3] = pack_h2(s[2 * kk + 1][2], s[2 * kk + 1][3]);
        }

        // O += P V  (V^T stored [d][t] so non-trans ldmatrix works)
        #pragma unroll
        for (int kk = 0; kk < 4; kk++) {
            #pragma unroll
            for (int db = 0; db < 4; db++) {
                uint32_t bb[4];
                LDSM_X4(bb[0], bb[1], bb[2], bb[3],
                        vb + (db * 16 + (lid & 7) + ((lid >> 4) << 3)) * 144
                        + ((lid >> 3) & 1) * 16 + kk * 32);
                MMA16816(o[db * 2], ap[kk][0], ap[kk][1], ap[kk][2], ap[kk][3],
                         bb[0], bb[1]);
                MMA16816(o[db * 2 + 1], ap[kk][0], ap[kk][1], ap[kk][2], ap[kk][3],
                         bb[2], bb[3]);
            }
        }
    }

    // epilogue
    l0 += __shfl_xor_sync(0xffffffffu, l0, 1, 4);
    l0 += __shfl_xor_sync(0xffffffffu, l0, 2, 4);
    l1 += __shfl_xor_sync(0xffffffffu, l1, 1, 4);
    l1 += __shfl_xor_sync(0xffffffffu, l1, 2, 4);
    float inv0 = 1.0f / l0, inv1 = 1.0f / l1;
    size_t row0 = (size_t)b * T_SEQ + q0 + r0loc;
    #pragma unroll
    for (int idx = 0; idx < 8; idx++) {
        int d = (idx >> 1) * 16 + (idx & 1) * 8 + (lid & 3) * 2;
        float2 u0, u1;
        u0.x = o[idx][0] * inv0; u0.y = o[idx][1] * inv0;
        u1.x = o[idx][2] * inv1; u1.y = o[idx][3] * inv1;
        *(float2*)&Og[row0 * EMB + h * HD + d] = u0;
        *(float2*)&Og[(row0 + 8) * EMB + h * HD + d] = u1;
    }
}

// ---------------- launch -----------------------------------------------------
extern "C" void kernel_launch(void* const* d_in, const int* in_sizes, int n_in,
                              void* d_out, int out_size) {
    const float* query = (const float*)d_in[0];
    const float* key_  = (const float*)d_in[1];
    const float* value = (const float*)d_in[2];
    const float* Wq = (const float*)d_in[3];
    const float* bq = (const float*)d_in[4];
    const float* Wk = (const float*)d_in[5];
    const float* bk = (const float*)d_in[6];
    const float* Wv = (const float*)d_in[7];
    const float* bv = (const float*)d_in[8];
    const float* Wo = (const float*)d_in[9];
    const float* bo = (const float*)d_in[10];
    const float* bias_table = (const float*)d_in[11];
    const float* offset     = (const float*)d_in[12];
    float* out = (float*)d_out;

    void *pq, *pk, *pv, *po, *pb, *pa3, *pw3, *pq16, *pk16, *pv16t;
    cudaGetSymbolAddress(&pq, g_q);
    cudaGetSymbolAddress(&pk, g_k);
    cudaGetSymbolAddress(&pv, g_v);
    cudaGetSymbolAddress(&po, g_o);
    cudaGetSymbolAddress(&pb, g_bias);
    cudaGetSymbolAddress(&pa3, g_a3);
    cudaGetSymbolAddress(&pw3, g_w3);
    cudaGetSymbolAddress(&pq16, g_q16);
    cudaGetSymbolAddress(&pk16, g_k16);
    cudaGetSymbolAddress(&pv16t, g_v16t);
    __half* a3 = (__half*)pa3;
    __half* w3 = (__half*)pw3;

    const int GEMM_SMEM = NSTG * ST_SZ;      // 110592
    cudaFuncSetAttribute(gemm_tc, cudaFuncAttributeMaxDynamicSharedMemorySize, GEMM_SMEM);
    cudaFuncSetAttribute(attn_mma, cudaFuncAttributeMaxDynamicSharedMemorySize, A_SMEM);

    dim3 ggrid(8, 64);

    bias_kernel<<<(NREL * NH + 255) / 256, 256>>>(bias_table, offset, (float*)pb);

    convert3<<<8192, 256>>>(query, a3, 8192, 0);
    convert3<<<1024, 256>>>(Wq, w3, 1024, 1);
    gemm_tc<<<ggrid, 256, GEMM_SMEM>>>(a3, w3, bq, (float*)pq);

    convert3<<<8192, 256>>>(key_, a3, 8192, 0);
    convert3<<<1024, 256>>>(Wk, w3, 1024, 1);
    gemm_tc<<<ggrid, 256, GEMM_SMEM>>>(a3, w3, bk, (float*)pk);

    convert3<<<8192, 256>>>(value, a3, 8192, 0);
    convert3<<<1024, 256>>>(Wv, w3, 1024, 1);
    gemm_tc<<<ggrid, 256, GEMM_SMEM>>>(a3, w3, bv, (float*)pv);

    conv16<<<8192, 256>>>((const float*)pq, (__half*)pq16);
    conv16<<<8192, 256>>>((const float*)pk, (__half*)pk16);
    conv16t<<<8192, 256>>>((const float*)pv, (__half*)pv16t);

    attn_mma<<<dim3(8, 128), 256, A_SMEM>>>(
        (const __half*)pq16, (const __half*)pk16, (const __half*)pv16t,
        (const float*)pb, (float*)po);

    convert3<<<8192, 256>>>((const float*)po, a3, 8192, 0);
    convert3<<<1024, 256>>>(Wo, w3, 1024, 1);
    gemm_tc<<<ggrid, 256, GEMM_SMEM>>>(a3, w3, bo, out);
}

// round 8
// speedup vs baseline: 3.1602x; 1.0807x over previous
#include <cuda_runtime.h>
#include <cuda_fp16.h>
#include <cstdint>
#include <math.h>

#define T_SEQ 1024
#define EMB   1024
#define NH    16
#define HD    64
#define BATCH 8
#define NREL  2047
#define K3    3072
#define KCH   48
#define NSTG  3

// ---------------- scratch (device globals) ----------------------------------
__device__ __align__(16) float g_bias[NREL * NH];      // [h][rel]
__device__ __align__(16) __half g_a3[25165824];        // [8192, 3072]
__device__ __align__(16) __half g_w3[3145728];         // [1024, 3072]
__device__ __align__(16) __half g_q16[8388608];        // [bh][t][d]
__device__ __align__(16) __half g_k16[8388608];        // [bh][t][d]
__device__ __align__(16) __half g_v16t[8388608];       // [bh][d][t]

// ---------------- PTX helpers ------------------------------------------------
__device__ __forceinline__ uint32_t smem_u32(const void* p) {
    uint32_t a;
    asm("{ .reg .u64 t; cvta.to.shared.u64 t, %1; cvt.u32.u64 %0, t; }"
        : "=r"(a) : "l"(p));
    return a;
}

#define CP_ASYNC16(dst, src) \
    asm volatile("cp.async.cg.shared.global [%0], [%1], 16;" :: "r"(dst), "l"(src))
#define CP_COMMIT() asm volatile("cp.async.commit_group;" ::: "memory")
#define CP_WAIT1()  asm volatile("cp.async.wait_group 1;" ::: "memory")
#define CP_WAIT0()  asm volatile("cp.async.wait_group 0;" ::: "memory")

#define LDSM_X4(r0, r1, r2, r3, addr) \
    asm volatile("ldmatrix.sync.aligned.m8n8.x4.shared.b16 {%0,%1,%2,%3}, [%4];" \
        : "=r"(r0), "=r"(r1), "=r"(r2), "=r"(r3) : "r"(addr))

#define MMA16816(d, a0, a1, a2, a3, b0, b1) \
    asm volatile("mma.sync.aligned.m16n8k16.row.col.f32.f16.f16.f32 " \
        "{%0,%1,%2,%3},{%4,%5,%6,%7},{%8,%9},{%0,%1,%2,%3};" \
        : "+f"((d)[0]), "+f"((d)[1]), "+f"((d)[2]), "+f"((d)[3]) \
        : "r"(a0), "r"(a1), "r"(a2), "r"(a3), "r"(b0), "r"(b1))

__device__ __forceinline__ uint32_t pack_h2(float a, float b) {
    __half2 h = __float22half2_rn(make_float2(a, b));
    return *reinterpret_cast<uint32_t*>(&h);
}

// ---------------- kernel 1: bias interpolation -> [h][rel] ------------------
__global__ void bias_kernel(const float* __restrict__ table,
                            const float* __restrict__ offset,
                            float* __restrict__ out) {
    int idx = blockIdx.x * 256 + threadIdx.x;
    if (idx >= NREL * NH) return;
    int r = idx / NH, h = idx % NH;
    float bounded = tanhf(offset[0]) * 0.5f;
    float adj = fminf(fmaxf((float)r + bounded, 0.0f), 2046.0f);
    float lof = floorf(adj);
    int lo = (int)lof;
    int hi = (int)ceilf(adj);
    float w = adj - lof;
    out[h * NREL + r] = table[lo * NH + h] * (1.0f - w) + table[hi * NH + h] * w;
}

// ---------------- kernel 2: fp32 -> fp16 hi/lo split, K-tripled --------------
__global__ void convert3(const float* __restrict__ in, __half* __restrict__ out,
                         int rows, int mode) {
    size_t idx = ((size_t)blockIdx.x * 256 + threadIdx.x) * 4;
    if (idx >= (size_t)rows * 1024) return;
    size_t row = idx >> 10;
    int col = (int)(idx & 1023);
    float4 x = *(const float4*)&in[idx];
    __half h0 = __float2half_rn(x.x), h1 = __float2half_rn(x.y);
    __half h2 = __float2half_rn(x.z), h3 = __float2half_rn(x.w);
    __half l0 = __float2half_rn(x.x - __half2float(h0));
    __half l1 = __float2half_rn(x.y - __half2float(h1));
    __half l2 = __float2half_rn(x.z - __half2float(h2));
    __half l3 = __float2half_rn(x.w - __half2float(h3));
    __half2 hA, hB, lA, lB;
    hA.x = h0; hA.y = h1; hB.x = h2; hB.y = h3;
    lA.x = l0; lA.y = l1; lB.x = l2; lB.y = l3;
    __half2* o0 = (__half2*)&out[row * K3 + col];
    __half2* o1 = (__half2*)&out[row * K3 + 1024 + col];
    __half2* o2 = (__half2*)&out[row * K3 + 2048 + col];
    o0[0] = hA; o0[1] = hB;
    if (mode == 0) { o1[0] = hA; o1[1] = hB; o2[0] = lA; o2[1] = lB; }
    else           { o1[0] = lA; o1[1] = lB; o2[0] = hA; o2[1] = hB; }
}

// ---------------- kernel 3: mma.sync fp16 GEMM, 64x64 warp tiles ------------
// A3 [8192,3072], W3 [1024,3072]; CTA 128x128, 4 warps (2x2 of 64x64).
// 3-stage cp.async pipeline. Epilogue modes:
//   0: fp32 row-major [8192,1024] + bias (final output)
//   1: fp16 [bh][t][d] + bias (Q, K)
//   2: fp16 [bh][d][t] + bias (V transposed)
#define ST_A   18432
#define ST_SZ  36864
__global__ void __launch_bounds__(128, 2)
gemm_tc(const __half* __restrict__ A, const __half* __restrict__ Bm,
        const float* __restrict__ bias, float* __restrict__ outF,
        __half* __restrict__ outH, int mode)
{
    extern __shared__ __align__(128) char smem[];
    uint32_t sbase = smem_u32(smem);

    int tid = threadIdx.x;
    int wid = tid >> 5, lid = tid & 31;
    int wm = wid >> 1, wn = wid & 1;          // 2x2 warp grid, 64x64 tiles
    size_t bm = (size_t)blockIdx.y * 128;
    size_t bn = (size_t)blockIdx.x * 128;

    const __half* gA = A + bm * K3;
    const __half* gB = Bm + bn * K3;

    int ldrow = tid >> 3;          // 0..15 (+16 stride, 8 iters)
    int ldch  = tid & 7;

    #pragma unroll
    for (int s = 0; s < NSTG - 1; s++) {
        uint32_t st = sbase + s * ST_SZ;
        #pragma unroll
        for (int i = 0; i < 8; i++) {
            int row = ldrow + i * 16;
            CP_ASYNC16(st + row * 144 + ldch * 16,
                       gA + (size_t)row * K3 + s * 64 + ldch * 8);
            CP_ASYNC16(st + ST_A + row * 144 + ldch * 16,
                       gB + (size_t)row * K3 + s * 64 + ldch * 8);
        }
        CP_COMMIT();
    }

    float acc[4][8][4];
    #pragma unroll
    for (int mi = 0; mi < 4; mi++)
        #pragma unroll
        for (int ni = 0; ni < 8; ni++)
            #pragma unroll
            for (int e = 0; e < 4; e++) acc[mi][ni][e] = 0.0f;

    uint32_t aOff = (uint32_t)((wm * 64 + (lid & 15)) * 144 + (lid >> 4) * 16);
    uint32_t bOff = (uint32_t)(ST_A +
        (wn * 64 + (lid & 7) + ((lid >> 4) << 3)) * 144 + ((lid >> 3) & 1) * 16);

    int cs = 0, ls = NSTG - 1;
    for (int c = 0; c < KCH; c++) {
        CP_WAIT1();
        __syncthreads();

        if (c + NSTG - 1 < KCH) {
            int cc = c + NSTG - 1;
            uint32_t st = sbase + ls * ST_SZ;
            #pragma unroll
            for (int i = 0; i < 8; i++) {
                int row = ldrow + i * 16;
                CP_ASYNC16(st + row * 144 + ldch * 16,
                           gA + (size_t)row * K3 + cc * 64 + ldch * 8);
                CP_ASYNC16(st + ST_A + row * 144 + ldch * 16,
                           gB + (size_t)row * K3 + cc * 64 + ldch * 8);
            }
        }
        CP_COMMIT();

        uint32_t st = sbase + cs * ST_SZ;
        #pragma unroll
        for (int kk = 0; kk < 4; kk++) {
            uint32_t a[4][4], b[4][4];
            #pragma unroll
            for (int mi = 0; mi < 4; mi++)
                LDSM_X4(a[mi][0], a[mi][1], a[mi][2], a[mi][3],
                        st + aOff + mi * (16 * 144) + kk * 32);
            #pragma unroll
            for (int nb = 0; nb < 4; nb++)
                LDSM_X4(b[nb][0], b[nb][1], b[nb][2], b[nb][3],
                        st + bOff + nb * (16 * 144) + kk * 32);
            #pragma unroll
            for (int mi = 0; mi < 4; mi++)
                #pragma unroll
                for (int nb = 0; nb < 4; nb++) {
                    MMA16816(acc[mi][nb * 2],
                             a[mi][0], a[mi][1], a[mi][2], a[mi][3],
                             b[nb][0], b[nb][1]);
                    MMA16816(acc[mi][nb * 2 + 1],
                             a[mi][0], a[mi][1], a[mi][2], a[mi][3],
                             b[nb][2], b[nb][3]);
                }
        }
        cs = (cs == NSTG - 1) ? 0 : cs + 1;
        ls = (ls == NSTG - 1) ? 0 : ls + 1;
    }

    // ---- epilogue ----
    #pragma unroll
    for (int mi = 0; mi < 4; mi++) {
        size_t r0 = bm + wm * 64 + mi * 16 + (lid >> 2);
        #pragma unroll
        for (int ni = 0; ni < 8; ni++) {
            size_t col = bn + wn * 64 + ni * 8 + (lid & 3) * 2;
            float2 bv = *(const float2*)&bias[col];
            float v00 = acc[mi][ni][0] + bv.x, v01 = acc[mi][ni][1] + bv.y;
            float v10 = acc[mi][ni][2] + bv.x, v11 = acc[mi][ni][3] + bv.y;
            if (mode == 0) {
                *(float2*)&outF[r0 * 1024 + col] = make_float2(v00, v01);
                *(float2*)&outF[(r0 + 8) * 1024 + col] = make_float2(v10, v11);
            } else if (mode == 1) {
                // [bh][t][d]
                int h = (int)(col >> 6), d = (int)(col & 63);
                size_t b0 = r0 >> 10, t0 = r0 & 1023;
                __half2* d0 = (__half2*)&outH[(((b0 * NH + h) * T_SEQ + t0) * HD + d)];
                *d0 = __float22half2_rn(make_float2(v00, v01));
                size_t r1 = r0 + 8;
                __half2* d1 = (__half2*)&outH[(((r1 >> 10) * NH + h) * T_SEQ + (r1 & 1023)) * HD + d];
                *d1 = __float22half2_rn(make_float2(v10, v11));
            } else {
                // [bh][d][t] transposed
                int h = (int)(col >> 6), d = (int)(col & 63);
                size_t b0 = r0 >> 10, t0 = r0 & 1023;
                size_t base = ((b0 * NH + h) * HD + d) * T_SEQ;
                outH[base + t0] = __float2half_rn(v00);
                outH[base + T_SEQ + t0] = __float2half_rn(v01);
                outH[base + t0 + 8] = __float2half_rn(v10);
                outH[base + T_SEQ + t0 + 8] = __float2half_rn(v11);
            }
        }
    }
}

// ---------------- kernel 4: fp16 mma flash attention -------------------------
// grid (8, 128): q-tile 128, one (b,h)/CTA, 8 warps x 16 rows, K-tile 64,
// double-buffered. Output: tripled hi/lo fp16 rows of g_a3 [row][3072].
#define A_SQ   0
#define A_SK   18432
#define A_SV   36864
#define A_SB   55296
#define A_SMEM 59904
__global__ void __launch_bounds__(256)
attn_mma(const __half* __restrict__ Q16, const __half* __restrict__ K16,
         const __half* __restrict__ V16t, const float* __restrict__ biasT,
         __half* __restrict__ Oa3)
{
    extern __shared__ __align__(128) char smem[];
    uint32_t sbase = smem_u32(smem);
    float* sbias = (float*)(smem + A_SB);

    int bh = blockIdx.y;
    int h = bh & (NH - 1), b = bh >> 4;
    int q0 = blockIdx.x * 128;
    int tid = threadIdx.x;
    int w = tid >> 5, lid = tid & 31;

    const __half* gQ = Q16 + ((size_t)bh * T_SEQ + q0) * HD;
    const __half* gK = K16 + (size_t)bh * T_SEQ * HD;
    const __half* gV = V16t + (size_t)bh * HD * T_SEQ;

    {
        #pragma unroll
        for (int i = 0; i < 4; i++) {
            int id = tid + i * 256;
            int row = id >> 3, ch = id & 7;
            CP_ASYNC16(sbase + A_SQ + row * 144 + ch * 16,
                       gQ + (size_t)row * HD + ch * 8);
        }
        #pragma unroll
        for (int i = 0; i < 2; i++) {
            int id = tid + i * 256;
            int row = id >> 3, ch = id & 7;
            CP_ASYNC16(sbase + A_SK + row * 144 + ch * 16,
                       gK + (size_t)row * HD + ch * 8);
            CP_ASYNC16(sbase + A_SV + row * 144 + ch * 16,
                       gV + (size_t)row * T_SEQ + ch * 8);
        }
        CP_COMMIT();
    }
    for (int j = tid; j < 1151; j += 256)
        sbias[j] = biasT[h * NREL + q0 + j];

    float o[8][4];
    #pragma unroll
    for (int i = 0; i < 8; i++)
        #pragma unroll
        for (int e = 0; e < 4; e++) o[i][e] = 0.0f;
    float m0 = -1e30f, m1 = -1e30f, l0 = 0.0f, l1 = 0.0f;
    uint32_t qa[4][4];

    int r0loc = w * 16 + (lid >> 2);

    for (int it = 0; it < 16; it++) {
        CP_WAIT0();
        __syncthreads();

        if (it < 15) {
            int kt2 = (it + 1) * 64;
            uint32_t bo = ((it + 1) & 1) * 9216;
            #pragma unroll
            for (int i = 0; i < 2; i++) {
                int id = tid + i * 256;
                int row = id >> 3, ch = id & 7;
                CP_ASYNC16(sbase + A_SK + bo + row * 144 + ch * 16,
                           gK + (size_t)(kt2 + row) * HD + ch * 8);
                CP_ASYNC16(sbase + A_SV + bo + row * 144 + ch * 16,
                           gV + (size_t)row * T_SEQ + kt2 + ch * 8);
            }
        }
        CP_COMMIT();

        if (it == 0) {
            #pragma unroll
            for (int kk = 0; kk < 4; kk++)
                LDSM_X4(qa[kk][0], qa[kk][1], qa[kk][2], qa[kk][3],
                        sbase + A_SQ + (w * 16 + (lid & 15)) * 144
                        + (lid >> 4) * 16 + kk * 32);
        }

        uint32_t kb = sbase + A_SK + (it & 1) * 9216;
        uint32_t vb = sbase + A_SV + (it & 1) * 9216;

        float s[8][4];
        #pragma unroll
        for (int i = 0; i < 8; i++)
            #pragma unroll
            for (int e = 0; e < 4; e++) s[i][e] = 0.0f;
        #pragma unroll
        for (int kk = 0; kk < 4; kk++) {
            #pragma unroll
            for (int nb = 0; nb < 4; nb++) {
                uint32_t bb[4];
                LDSM_X4(bb[0], bb[1], bb[2], bb[3],
                        kb + (nb * 16 + (lid & 7) + ((lid >> 4) << 3)) * 144
                        + ((lid >> 3) & 1) * 16 + kk * 32);
                MMA16816(s[nb * 2], qa[kk][0], qa[kk][1], qa[kk][2], qa[kk][3],
                         bb[0], bb[1]);
                MMA16816(s[nb * 2 + 1], qa[kk][0], qa[kk][1], qa[kk][2], qa[kk][3],
                         bb[2], bb[3]);
            }
        }

        int kcol = it * 64 + (lid & 3) * 2;
        #pragma unroll
        for (int nt = 0; nt < 8; nt++) {
            int jb = r0loc + 1023 - (kcol + nt * 8);
            s[nt][0] = s[nt][0] * 0.125f + sbias[jb];
            s[nt][1] = s[nt][1] * 0.125f + sbias[jb - 1];
            s[nt][2] = s[nt][2] * 0.125f + sbias[jb + 8];
            s[nt][3] = s[nt][3] * 0.125f + sbias[jb + 7];
        }

        float mx0 = -1e30f, mx1 = -1e30f;
        #pragma unroll
        for (int nt = 0; nt < 8; nt++) {
            mx0 = fmaxf(mx0, fmaxf(s[nt][0], s[nt][1]));
            mx1 = fmaxf(mx1, fmaxf(s[nt][2], s[nt][3]));
        }
        mx0 = fmaxf(mx0, __shfl_xor_sync(0xffffffffu, mx0, 1, 4));
        mx0 = fmaxf(mx0, __shfl_xor_sync(0xffffffffu, mx0, 2, 4));
        mx1 = fmaxf(mx1, __shfl_xor_sync(0xffffffffu, mx1, 1, 4));
        mx1 = fmaxf(mx1, __shfl_xor_sync(0xffffffffu, mx1, 2, 4));
        float mn0 = fmaxf(m0, mx0), mn1 = fmaxf(m1, mx1);
        float c0 = __expf(m0 - mn0), c1 = __expf(m1 - mn1);
        m0 = mn0; m1 = mn1;
        float ls0 = 0.0f, ls1 = 0.0f;
        #pragma unroll
        for (int nt = 0; nt < 8; nt++) {
            s[nt][0] = __expf(s[nt][0] - mn0); ls0 += s[nt][0];
            s[nt][1] = __expf(s[nt][1] - mn0); ls0 += s[nt][1];
            s[nt][2] = __expf(s[nt][2] - mn1); ls1 += s[nt][2];
            s[nt][3] = __expf(s[nt][3] - mn1); ls1 += s[nt][3];
        }
        l0 = l0 * c0 + ls0;
        l1 = l1 * c1 + ls1;
        #pragma unroll
        for (int dn = 0; dn < 8; dn++) {
            o[dn][0] *= c0; o[dn][1] *= c0;
            o[dn][2] *= c1; o[dn][3] *= c1;
        }

        uint32_t ap[4][4];
        #pragma unroll
        for (int kk = 0; kk < 4; kk++) {
            ap[kk][0] = pack_h2(s[2 * kk][0], s[2 * kk][1]);
            ap[kk][1] = pack_h2(s[2 * kk][2], s[2 * kk][3]);
            ap[kk][2] = pack_h2(s[2 * kk + 1][0], s[2 * kk + 1][1]);
            ap[kk][3] = pack_h2(s[2 * kk + 1][2], s[2 * kk + 1][3]);
        }

        #pragma unroll
        for (int kk = 0; kk < 4; kk++) {
            #pragma unroll
            for (int db = 0; db < 4; db++) {
                uint32_t bb[4];
                LDSM_X4(bb[0], bb[1], bb[2], bb[3],
                        vb + (db * 16 + (lid & 7) + ((lid >> 4) << 3)) * 144
                        + ((lid >> 3) & 1) * 16 + kk * 32);
                MMA16816(o[db * 2], ap[kk][0], ap[kk][1], ap[kk][2], ap[kk][3],
                         bb[0], bb[1]);
                MMA16816(o[db * 2 + 1], ap[kk][0], ap[kk][1], ap[kk][2], ap[kk][3],
                         bb[2], bb[3]);
            }
        }
    }

    // epilogue -> tripled hi/lo fp16 directly into a3 [row][3072]
    l0 += __shfl_xor_sync(0xffffffffu, l0, 1, 4);
    l0 += __shfl_xor_sync(0xffffffffu, l0, 2, 4);
    l1 += __shfl_xor_sync(0xffffffffu, l1, 1, 4);
    l1 += __shfl_xor_sync(0xffffffffu, l1, 2, 4);
    float inv0 = 1.0f / l0, inv1 = 1.0f / l1;
    size_t row0 = (size_t)b * T_SEQ + q0 + r0loc;
    #pragma unroll
    for (int idx = 0; idx < 8; idx++) {
        int d = (idx >> 1) * 16 + (idx & 1) * 8 + (lid & 3) * 2;
        int col = h * HD + d;
        float v00 = o[idx][0] * inv0, v01 = o[idx][1] * inv0;
        float v10 = o[idx][2] * inv1, v11 = o[idx][3] * inv1;
        __half h00 = __float2half_rn(v00), h01 = __float2half_rn(v01);
        __half h10 = __float2half_rn(v10), h11 = __float2half_rn(v11);
        __half2 hi0; hi0.x = h00; hi0.y = h01;
        __half2 hi1; hi1.x = h10; hi1.y = h11;
        __half2 lo0, lo1;
        lo0.x = __float2half_rn(v00 - __half2float(h00));
        lo0.y = __float2half_rn(v01 - __half2float(h01));
        lo1.x = __float2half_rn(v10 - __half2float(h10));
        lo1.y = __float2half_rn(v11 - __half2float(h11));
        size_t b0 = row0 * K3 + col;
        size_t b1 = (row0 + 8) * K3 + col;
        *(__half2*)&Oa3[b0] = hi0;
        *(__half2*)&Oa3[b0 + 1024] = hi0;
        *(__half2*)&Oa3[b0 + 2048] = lo0;
        *(__half2*)&Oa3[b1] = hi1;
        *(__half2*)&Oa3[b1 + 1024] = hi1;
        *(__half2*)&Oa3[b1 + 2048] = lo1;
    }
}

// ---------------- launch -----------------------------------------------------
extern "C" void kernel_launch(void* const* d_in, const int* in_sizes, int n_in,
                              void* d_out, int out_size) {
    const float* query = (const float*)d_in[0];
    const float* key_  = (const float*)d_in[1];
    const float* value = (const float*)d_in[2];
    const float* Wq = (const float*)d_in[3];
    const float* bq = (const float*)d_in[4];
    const float* Wk = (const float*)d_in[5];
    const float* bk = (const float*)d_in[6];
    const float* Wv = (const float*)d_in[7];
    const float* bv = (const float*)d_in[8];
    const float* Wo = (const float*)d_in[9];
    const float* bo = (const float*)d_in[10];
    const float* bias_table = (const float*)d_in[11];
    const float* offset     = (const float*)d_in[12];
    float* out = (float*)d_out;

    void *pb, *pa3, *pw3, *pq16, *pk16, *pv16t;
    cudaGetSymbolAddress(&pb, g_bias);
    cudaGetSymbolAddress(&pa3, g_a3);
    cudaGetSymbolAddress(&pw3, g_w3);
    cudaGetSymbolAddress(&pq16, g_q16);
    cudaGetSymbolAddress(&pk16, g_k16);
    cudaGetSymbolAddress(&pv16t, g_v16t);
    __half* a3 = (__half*)pa3;
    __half* w3 = (__half*)pw3;

    const int GEMM_SMEM = NSTG * ST_SZ;      // 110592
    cudaFuncSetAttribute(gemm_tc, cudaFuncAttributeMaxDynamicSharedMemorySize, GEMM_SMEM);
    cudaFuncSetAttribute(attn_mma, cudaFuncAttributeMaxDynamicSharedMemorySize, A_SMEM);

    dim3 ggrid(8, 64);

    bias_kernel<<<(NREL * NH + 255) / 256, 256>>>(bias_table, offset, (float*)pb);

    convert3<<<8192, 256>>>(query, a3, 8192, 0);
    convert3<<<1024, 256>>>(Wq, w3, 1024, 1);
    gemm_tc<<<ggrid, 128, GEMM_SMEM>>>(a3, w3, bq, nullptr, (__half*)pq16, 1);

    convert3<<<8192, 256>>>(key_, a3, 8192, 0);
    convert3<<<1024, 256>>>(Wk, w3, 1024, 1);
    gemm_tc<<<ggrid, 128, GEMM_SMEM>>>(a3, w3, bk, nullptr, (__half*)pk16, 1);

    convert3<<<8192, 256>>>(value, a3, 8192, 0);
    convert3<<<1024, 256>>>(Wv, w3, 1024, 1);
    gemm_tc<<<ggrid, 128, GEMM_SMEM>>>(a3, w3, bv, nullptr, (__half*)pv16t, 2);

    attn_mma<<<dim3(8, 128), 256, A_SMEM>>>(
        (const __half*)pq16, (const __half*)pk16, (const __half*)pv16t,
        (const float*)pb, a3);

    convert3<<<1024, 256>>>(Wo, w3, 1024, 1);
    gemm_tc<<<ggrid, 128, GEMM_SMEM>>>(a3, w3, bo, out, nullptr, 0);
}

// round 9
// speedup vs baseline: 5.1751x; 1.6376x over previous
#include <cuda_runtime.h>
#include <cuda_fp16.h>
#include <cstdint>
#include <math.h>

#define T_SEQ 1024
#define EMB   1024
#define NH    16
#define HD    64
#define BATCH 8
#define NREL  2047
#define K3    3072
#define NSTG  3

// ---------------- scratch (device globals) ----------------------------------
__device__ __align__(16) float g_bias[NREL * NH];      // [h][rel]
__device__ __align__(16) __half g_a3[25165824];        // [8192, 3072] (also fp16 act [8192,1024])
__device__ __align__(16) __half g_w3[3145728];         // [1024, 3072] (also fp16 W [1024,1024])
__device__ __align__(16) __half g_q16[8388608];        // [bh][t][d]
__device__ __align__(16) __half g_k16[8388608];        // [bh][t][d]
__device__ __align__(16) __half g_v16t[8388608];       // [bh][d][t]

// ---------------- PTX helpers ------------------------------------------------
__device__ __forceinline__ uint32_t smem_u32(const void* p) {
    uint32_t a;
    asm("{ .reg .u64 t; cvta.to.shared.u64 t, %1; cvt.u32.u64 %0, t; }"
        : "=r"(a) : "l"(p));
    return a;
}

#define CP_ASYNC16(dst, src) \
    asm volatile("cp.async.cg.shared.global [%0], [%1], 16;" :: "r"(dst), "l"(src))
#define CP_COMMIT() asm volatile("cp.async.commit_group;" ::: "memory")
#define CP_WAIT1()  asm volatile("cp.async.wait_group 1;" ::: "memory")
#define CP_WAIT0()  asm volatile("cp.async.wait_group 0;" ::: "memory")

#define LDSM_X4(r0, r1, r2, r3, addr) \
    asm volatile("ldmatrix.sync.aligned.m8n8.x4.shared.b16 {%0,%1,%2,%3}, [%4];" \
        : "=r"(r0), "=r"(r1), "=r"(r2), "=r"(r3) : "r"(addr))

#define MMA16816(d, a0, a1, a2, a3, b0, b1) \
    asm volatile("mma.sync.aligned.m16n8k16.row.col.f32.f16.f16.f32 " \
        "{%0,%1,%2,%3},{%4,%5,%6,%7},{%8,%9},{%0,%1,%2,%3};" \
        : "+f"((d)[0]), "+f"((d)[1]), "+f"((d)[2]), "+f"((d)[3]) \
        : "r"(a0), "r"(a1), "r"(a2), "r"(a3), "r"(b0), "r"(b1))

__device__ __forceinline__ uint32_t pack_h2(float a, float b) {
    __half2 h = __float22half2_rn(make_float2(a, b));
    return *reinterpret_cast<uint32_t*>(&h);
}

// ---------------- kernel 1: bias interpolation -> [h][rel] ------------------
__global__ void bias_kernel(const float* __restrict__ table,
                            const float* __restrict__ offset,
                            float* __restrict__ out) {
    int idx = blockIdx.x * 256 + threadIdx.x;
    if (idx >= NREL * NH) return;
    int r = idx / NH, h = idx % NH;
    float bounded = tanhf(offset[0]) * 0.5f;
    float adj = fminf(fmaxf((float)r + bounded, 0.0f), 2046.0f);
    float lof = floorf(adj);
    int lo = (int)lof;
    int hi = (int)ceilf(adj);
    float w = adj - lof;
    out[h * NREL + r] = table[lo * NH + h] * (1.0f - w) + table[hi * NH + h] * w;
}

// ---------------- kernel 2a: plain fp32 -> fp16 (same layout) ----------------
__global__ void convert1(const float* __restrict__ in, __half* __restrict__ out,
                         int n4) {
    int idx = blockIdx.x * 256 + threadIdx.x;
    if (idx >= n4) return;
    float4 x = *(const float4*)&in[(size_t)idx * 4];
    __half2 p0 = __float22half2_rn(make_float2(x.x, x.y));
    __half2 p1 = __float22half2_rn(make_float2(x.z, x.w));
    __half2* dst = (__half2*)&out[(size_t)idx * 4];
    dst[0] = p0; dst[1] = p1;
}

// ---------------- kernel 2b: fp32 -> fp16 hi/lo split, K-tripled (weights) --
__global__ void convert3(const float* __restrict__ in, __half* __restrict__ out,
                         int rows, int mode) {
    size_t idx = ((size_t)blockIdx.x * 256 + threadIdx.x) * 4;
    if (idx >= (size_t)rows * 1024) return;
    size_t row = idx >> 10;
    int col = (int)(idx & 1023);
    float4 x = *(const float4*)&in[idx];
    __half h0 = __float2half_rn(x.x), h1 = __float2half_rn(x.y);
    __half h2 = __float2half_rn(x.z), h3 = __float2half_rn(x.w);
    __half l0 = __float2half_rn(x.x - __half2float(h0));
    __half l1 = __float2half_rn(x.y - __half2float(h1));
    __half l2 = __float2half_rn(x.z - __half2float(h2));
    __half l3 = __float2half_rn(x.w - __half2float(h3));
    __half2 hA, hB, lA, lB;
    hA.x = h0; hA.y = h1; hB.x = h2; hB.y = h3;
    lA.x = l0; lA.y = l1; lB.x = l2; lB.y = l3;
    __half2* o0 = (__half2*)&out[row * K3 + col];
    __half2* o1 = (__half2*)&out[row * K3 + 1024 + col];
    __half2* o2 = (__half2*)&out[row * K3 + 2048 + col];
    o0[0] = hA; o0[1] = hB;
    if (mode == 0) { o1[0] = hA; o1[1] = hB; o2[0] = lA; o2[1] = lB; }
    else           { o1[0] = lA; o1[1] = lB; o2[0] = hA; o2[1] = hB; }
}

// ---------------- kernel 3: mma.sync fp16 GEMM, 64x64 warp tiles ------------
// A [8192,kdim], W [1024,kdim]; CTA 128x128, 4 warps (2x2 of 64x64).
// 3-stage cp.async pipeline. Epilogue modes:
//   0: fp32 row-major [8192,1024] + bias (final output)
//   1: fp16 [bh][t][d] + bias (Q, K)
//   2: fp16 [bh][d][t] + bias (V transposed)
#define ST_A   18432
#define ST_SZ  36864
__global__ void __launch_bounds__(128, 2)
gemm_tc(const __half* __restrict__ A, const __half* __restrict__ Bm,
        const float* __restrict__ bias, float* __restrict__ outF,
        __half* __restrict__ outH, int mode, int kdim)
{
    extern __shared__ __align__(128) char smem[];
    uint32_t sbase = smem_u32(smem);

    int tid = threadIdx.x;
    int wid = tid >> 5, lid = tid & 31;
    int wm = wid >> 1, wn = wid & 1;
    size_t bm = (size_t)blockIdx.y * 128;
    size_t bn = (size_t)blockIdx.x * 128;
    int kch = kdim >> 6;

    const __half* gA = A + bm * kdim;
    const __half* gB = Bm + bn * kdim;

    int ldrow = tid >> 3;
    int ldch  = tid & 7;

    #pragma unroll
    for (int s = 0; s < NSTG - 1; s++) {
        uint32_t st = sbase + s * ST_SZ;
        #pragma unroll
        for (int i = 0; i < 8; i++) {
            int row = ldrow + i * 16;
            CP_ASYNC16(st + row * 144 + ldch * 16,
                       gA + (size_t)row * kdim + s * 64 + ldch * 8);
            CP_ASYNC16(st + ST_A + row * 144 + ldch * 16,
                       gB + (size_t)row * kdim + s * 64 + ldch * 8);
        }
        CP_COMMIT();
    }

    float acc[4][8][4];
    #pragma unroll
    for (int mi = 0; mi < 4; mi++)
        #pragma unroll
        for (int ni = 0; ni < 8; ni++)
            #pragma unroll
            for (int e = 0; e < 4; e++) acc[mi][ni][e] = 0.0f;

    uint32_t aOff = (uint32_t)((wm * 64 + (lid & 15)) * 144 + (lid >> 4) * 16);
    uint32_t bOff = (uint32_t)(ST_A +
        (wn * 64 + (lid & 7) + ((lid >> 4) << 3)) * 144 + ((lid >> 3) & 1) * 16);

    int cs = 0, ls = NSTG - 1;
    for (int c = 0; c < kch; c++) {
        CP_WAIT1();
        __syncthreads();

        if (c + NSTG - 1 < kch) {
            int cc = c + NSTG - 1;
            uint32_t st = sbase + ls * ST_SZ;
            #pragma unroll
            for (int i = 0; i < 8; i++) {
                int row = ldrow + i * 16;
                CP_ASYNC16(st + row * 144 + ldch * 16,
                           gA + (size_t)row * kdim + cc * 64 + ldch * 8);
                CP_ASYNC16(st + ST_A + row * 144 + ldch * 16,
                           gB + (size_t)row * kdim + cc * 64 + ldch * 8);
            }
        }
        CP_COMMIT();

        uint32_t st = sbase + cs * ST_SZ;
        #pragma unroll
        for (int kk = 0; kk < 4; kk++) {
            uint32_t a[4][4], b[4][4];
            #pragma unroll
            for (int mi = 0; mi < 4; mi++)
                LDSM_X4(a[mi][0], a[mi][1], a[mi][2], a[mi][3],
                        st + aOff + mi * (16 * 144) + kk * 32);
            #pragma unroll
            for (int nb = 0; nb < 4; nb++)
                LDSM_X4(b[nb][0], b[nb][1], b[nb][2], b[nb][3],
                        st + bOff + nb * (16 * 144) + kk * 32);
            #pragma unroll
            for (int mi = 0; mi < 4; mi++)
                #pragma unroll
                for (int nb = 0; nb < 4; nb++) {
                    MMA16816(acc[mi][nb * 2],
                             a[mi][0], a[mi][1], a[mi][2], a[mi][3],
                             b[nb][0], b[nb][1]);
                    MMA16816(acc[mi][nb * 2 + 1],
                             a[mi][0], a[mi][1], a[mi][2], a[mi][3],
                             b[nb][2], b[nb][3]);
                }
        }
        cs = (cs == NSTG - 1) ? 0 : cs + 1;
        ls = (ls == NSTG - 1) ? 0 : ls + 1;
    }

    // ---- epilogue ----
    #pragma unroll
    for (int mi = 0; mi < 4; mi++) {
        size_t r0 = bm + wm * 64 + mi * 16 + (lid >> 2);
        #pragma unroll
        for (int ni = 0; ni < 8; ni++) {
            size_t col = bn + wn * 64 + ni * 8 + (lid & 3) * 2;
            float2 bv = *(const float2*)&bias[col];
            float v00 = acc[mi][ni][0] + bv.x, v01 = acc[mi][ni][1] + bv.y;
            float v10 = acc[mi][ni][2] + bv.x, v11 = acc[mi][ni][3] + bv.y;
            if (mode == 0) {
                *(float2*)&outF[r0 * 1024 + col] = make_float2(v00, v01);
                *(float2*)&outF[(r0 + 8) * 1024 + col] = make_float2(v10, v11);
            } else if (mode == 1) {
                int h = (int)(col >> 6), d = (int)(col & 63);
                size_t b0 = r0 >> 10, t0 = r0 & 1023;
                __half2* d0 = (__half2*)&outH[(((b0 * NH + h) * T_SEQ + t0) * HD + d)];
                *d0 = __float22half2_rn(make_float2(v00, v01));
                size_t r1 = r0 + 8;
                __half2* d1 = (__half2*)&outH[(((r1 >> 10) * NH + h) * T_SEQ + (r1 & 1023)) * HD + d];
                *d1 = __float22half2_rn(make_float2(v10, v11));
            } else {
                int h = (int)(col >> 6), d = (int)(col & 63);
                size_t b0 = r0 >> 10, t0 = r0 & 1023;
                size_t base = ((b0 * NH + h) * HD + d) * T_SEQ;
                outH[base + t0] = __float2half_rn(v00);
                outH[base + T_SEQ + t0] = __float2half_rn(v01);
                outH[base + t0 + 8] = __float2half_rn(v10);
                outH[base + T_SEQ + t0 + 8] = __float2half_rn(v11);
            }
        }
    }
}

// ---------------- kernel 4: fp16 mma flash attention -------------------------
#define A_SQ   0
#define A_SK   18432
#define A_SV   36864
#define A_SB   55296
#define A_SMEM 59904
__global__ void __launch_bounds__(256)
attn_mma(const __half* __restrict__ Q16, const __half* __restrict__ K16,
         const __half* __restrict__ V16t, const float* __restrict__ biasT,
         __half* __restrict__ Oa3)
{
    extern __shared__ __align__(128) char smem[];
    uint32_t sbase = smem_u32(smem);
    float* sbias = (float*)(smem + A_SB);

    int bh = blockIdx.y;
    int h = bh & (NH - 1), b = bh >> 4;
    int q0 = blockIdx.x * 128;
    int tid = threadIdx.x;
    int w = tid >> 5, lid = tid & 31;

    const __half* gQ = Q16 + ((size_t)bh * T_SEQ + q0) * HD;
    const __half* gK = K16 + (size_t)bh * T_SEQ * HD;
    const __half* gV = V16t + (size_t)bh * HD * T_SEQ;

    {
        #pragma unroll
        for (int i = 0; i < 4; i++) {
            int id = tid + i * 256;
            int row = id >> 3, ch = id & 7;
            CP_ASYNC16(sbase + A_SQ + row * 144 + ch * 16,
                       gQ + (size_t)row * HD + ch * 8);
        }
        #pragma unroll
        for (int i = 0; i < 2; i++) {
            int id = tid + i * 256;
            int row = id >> 3, ch = id & 7;
            CP_ASYNC16(sbase + A_SK + row * 144 + ch * 16,
                       gK + (size_t)row * HD + ch * 8);
            CP_ASYNC16(sbase + A_SV + row * 144 + ch * 16,
                       gV + (size_t)row * T_SEQ + ch * 8);
        }
        CP_COMMIT();
    }
    for (int j = tid; j < 1151; j += 256)
        sbias[j] = biasT[h * NREL + q0 + j];

    float o[8][4];
    #pragma unroll
    for (int i = 0; i < 8; i++)
        #pragma unroll
        for (int e = 0; e < 4; e++) o[i][e] = 0.0f;
    float m0 = -1e30f, m1 = -1e30f, l0 = 0.0f, l1 = 0.0f;
    uint32_t qa[4][4];

    int r0loc = w * 16 + (lid >> 2);

    for (int it = 0; it < 16; it++) {
        CP_WAIT0();
        __syncthreads();

        if (it < 15) {
            int kt2 = (it + 1) * 64;
            uint32_t bo = ((it + 1) & 1) * 9216;
            #pragma unroll
            for (int i = 0; i < 2; i++) {
                int id = tid + i * 256;
                int row = id >> 3, ch = id & 7;
                CP_ASYNC16(sbase + A_SK + bo + row * 144 + ch * 16,
                           gK + (size_t)(kt2 + row) * HD + ch * 8);
                CP_ASYNC16(sbase + A_SV + bo + row * 144 + ch * 16,
                           gV + (size_t)row * T_SEQ + kt2 + ch * 8);
            }
        }
        CP_COMMIT();

        if (it == 0) {
            #pragma unroll
            for (int kk = 0; kk < 4; kk++)
                LDSM_X4(qa[kk][0], qa[kk][1], qa[kk][2], qa[kk][3],
                        sbase + A_SQ + (w * 16 + (lid & 15)) * 144
                        + (lid >> 4) * 16 + kk * 32);
        }

        uint32_t kb = sbase + A_SK + (it & 1) * 9216;
        uint32_t vb = sbase + A_SV + (it & 1) * 9216;

        float s[8][4];
        #pragma unroll
        for (int i = 0; i < 8; i++)
            #pragma unroll
            for (int e = 0; e < 4; e++) s[i][e] = 0.0f;
        #pragma unroll
        for (int kk = 0; kk < 4; kk++) {
            #pragma unroll
            for (int nb = 0; nb < 4; nb++) {
                uint32_t bb[4];
                LDSM_X4(bb[0], bb[1], bb[2], bb[3],
                        kb + (nb * 16 + (lid & 7) + ((lid >> 4) << 3)) * 144
                        + ((lid >> 3) & 1) * 16 + kk * 32);
                MMA16816(s[nb * 2], qa[kk][0], qa[kk][1], qa[kk][2], qa[kk][3],
                         bb[0], bb[1]);
                MMA16816(s[nb * 2 + 1], qa[kk][0], qa[kk][1], qa[kk][2], qa[kk][3],
                         bb[2], bb[3]);
            }
        }

        int kcol = it * 64 + (lid & 3) * 2;
        #pragma unroll
        for (int nt = 0; nt < 8; nt++) {
            int jb = r0loc + 1023 - (kcol + nt * 8);
            s[nt][0] = s[nt][0] * 0.125f + sbias[jb];
            s[nt][1] = s[nt][1] * 0.125f + sbias[jb - 1];
            s[nt][2] = s[nt][2] * 0.125f + sbias[jb + 8];
            s[nt][3] = s[nt][3] * 0.125f + sbias[jb + 7];
        }

        float mx0 = -1e30f, mx1 = -1e30f;
        #pragma unroll
        for (int nt = 0; nt < 8; nt++) {
            mx0 = fmaxf(mx0, fmaxf(s[nt][0], s[nt][1]));
            mx1 = fmaxf(mx1, fmaxf(s[nt][2], s[nt][3]));
        }
        mx0 = fmaxf(mx0, __shfl_xor_sync(0xffffffffu, mx0, 1, 4));
        mx0 = fmaxf(mx0, __shfl_xor_sync(0xffffffffu, mx0, 2, 4));
        mx1 = fmaxf(mx1, __shfl_xor_sync(0xffffffffu, mx1, 1, 4));
        mx1 = fmaxf(mx1, __shfl_xor_sync(0xffffffffu, mx1, 2, 4));
        float mn0 = fmaxf(m0, mx0), mn1 = fmaxf(m1, mx1);
        float c0 = __expf(m0 - mn0), c1 = __expf(m1 - mn1);
        m0 = mn0; m1 = mn1;
        float ls0 = 0.0f, ls1 = 0.0f;
        #pragma unroll
        for (int nt = 0; nt < 8; nt++) {
            s[nt][0] = __expf(s[nt][0] - mn0); ls0 += s[nt][0];
            s[nt][1] = __expf(s[nt][1] - mn0); ls0 += s[nt][1];
            s[nt][2] = __expf(s[nt][2] - mn1); ls1 += s[nt][2];
            s[nt][3] = __expf(s[nt][3] - mn1); ls1 += s[nt][3];
        }
        l0 = l0 * c0 + ls0;
        l1 = l1 * c1 + ls1;
        #pragma unroll
        for (int dn = 0; dn < 8; dn++) {
            o[dn][0] *= c0; o[dn][1] *= c0;
            o[dn][2] *= c1; o[dn][3] *= c1;
        }

        uint32_t ap[4][4];
        #pragma unroll
        for (int kk = 0; kk < 4; kk++) {
            ap[kk][0] = pack_h2(s[2 * kk][0], s[2 * kk][1]);
            ap[kk][1] = pack_h2(s[2 * kk][2], s[2 * kk][3]);
            ap[kk][2] = pack_h2(s[2 * kk + 1][0], s[2 * kk + 1][1]);
            ap[kk][3] = pack_h2(s[2 * kk + 1][2], s[2 * kk + 1][3]);
        }

        #pragma unroll
        for (int kk = 0; kk < 4; kk++) {
            #pragma unroll
            for (int db = 0; db < 4; db++) {
                uint32_t bb[4];
                LDSM_X4(bb[0], bb[1], bb[2], bb[3],
                        vb + (db * 16 + (lid & 7) + ((lid >> 4) << 3)) * 144
                        + ((lid >> 3) & 1) * 16 + kk * 32);
                MMA16816(o[db * 2], ap[kk][0], ap[kk][1], ap[kk][2], ap[kk][3],
                         bb[0], bb[1]);
                MMA16816(o[db * 2 + 1], ap[kk][0], ap[kk][1], ap[kk][2], ap[kk][3],
                         bb[2], bb[3]);
            }
        }
    }

    // epilogue -> tripled hi/lo fp16 directly into a3 [row][3072]
    l0 += __shfl_xor_sync(0xffffffffu, l0, 1, 4);
    l0 += __shfl_xor_sync(0xffffffffu, l0, 2, 4);
    l1 += __shfl_xor_sync(0xffffffffu, l1, 1, 4);
    l1 += __shfl_xor_sync(0xffffffffu, l1, 2, 4);
    float inv0 = 1.0f / l0, inv1 = 1.0f / l1;
    size_t row0 = (size_t)b * T_SEQ + q0 + r0loc;
    #pragma unroll
    for (int idx = 0; idx < 8; idx++) {
        int d = (idx >> 1) * 16 + (idx & 1) * 8 + (lid & 3) * 2;
        int col = h * HD + d;
        float v00 = o[idx][0] * inv0, v01 = o[idx][1] * inv0;
        float v10 = o[idx][2] * inv1, v11 = o[idx][3] * inv1;
        __half h00 = __float2half_rn(v00), h01 = __float2half_rn(v01);
        __half h10 = __float2half_rn(v10), h11 = __float2half_rn(v11);
        __half2 hi0; hi0.x = h00; hi0.y = h01;
        __half2 hi1; hi1.x = h10; hi1.y = h11;
        __half2 lo0, lo1;
        lo0.x = __float2half_rn(v00 - __half2float(h00));
        lo0.y = __float2half_rn(v01 - __half2float(h01));
        lo1.x = __float2half_rn(v10 - __half2float(h10));
        lo1.y = __float2half_rn(v11 - __half2float(h11));
        size_t b0 = row0 * K3 + col;
        size_t b1 = (row0 + 8) * K3 + col;
        *(__half2*)&Oa3[b0] = hi0;
        *(__half2*)&Oa3[b0 + 1024] = hi0;
        *(__half2*)&Oa3[b0 + 2048] = lo0;
        *(__half2*)&Oa3[b1] = hi1;
        *(__half2*)&Oa3[b1 + 1024] = hi1;
        *(__half2*)&Oa3[b1 + 2048] = lo1;
    }
}

// ---------------- launch -----------------------------------------------------
extern "C" void kernel_launch(void* const* d_in, const int* in_sizes, int n_in,
                              void* d_out, int out_size) {
    const float* query = (const float*)d_in[0];
    const float* key_  = (const float*)d_in[1];
    const float* value = (const float*)d_in[2];
    const float* Wq = (const float*)d_in[3];
    const float* bq = (const float*)d_in[4];
    const float* Wk = (const float*)d_in[5];
    const float* bk = (const float*)d_in[6];
    const float* Wv = (const float*)d_in[7];
    const float* bv = (const float*)d_in[8];
    const float* Wo = (const float*)d_in[9];
    const float* bo = (const float*)d_in[10];
    const float* bias_table = (const float*)d_in[11];
    const float* offset     = (const float*)d_in[12];
    float* out = (float*)d_out;

    void *pb, *pa3, *pw3, *pq16, *pk16, *pv16t;
    cudaGetSymbolAddress(&pb, g_bias);
    cudaGetSymbolAddress(&pa3, g_a3);
    cudaGetSymbolAddress(&pw3, g_w3);
    cudaGetSymbolAddress(&pq16, g_q16);
    cudaGetSymbolAddress(&pk16, g_k16);
    cudaGetSymbolAddress(&pv16t, g_v16t);
    __half* a3 = (__half*)pa3;       // reused: fp16 activations [8192,1024] / tripled [8192,3072]
    __half* w3 = (__half*)pw3;       // reused: fp16 weights [1024,1024] / tripled [1024,3072]

    const int GEMM_SMEM = NSTG * ST_SZ;      // 110592
    cudaFuncSetAttribute(gemm_tc, cudaFuncAttributeMaxDynamicSharedMemorySize, GEMM_SMEM);
    cudaFuncSetAttribute(attn_mma, cudaFuncAttributeMaxDynamicSharedMemorySize, A_SMEM);

    dim3 ggrid(8, 64);

    bias_kernel<<<(NREL * NH + 255) / 256, 256>>>(bias_table, offset, (float*)pb);

    // Q/K/V projections: pure fp16, K=1024
    convert1<<<8192, 256>>>(query, a3, 8192 * 256);
    convert1<<<1024, 256>>>(Wq, w3, 1024 * 256);
    gemm_tc<<<ggrid, 128, GEMM_SMEM>>>(a3, w3, bq, nullptr, (__half*)pq16, 1, 1024);

    convert1<<<8192, 256>>>(key_, a3, 8192 * 256);
    convert1<<<1024, 256>>>(Wk, w3, 1024 * 256);
    gemm_tc<<<ggrid, 128, GEMM_SMEM>>>(a3, w3, bk, nullptr, (__half*)pk16, 1, 1024);

    convert1<<<8192, 256>>>(value, a3, 8192 * 256);
    convert1<<<1024, 256>>>(Wv, w3, 1024 * 256);
    gemm_tc<<<ggrid, 128, GEMM_SMEM>>>(a3, w3, bv, nullptr, (__half*)pv16t, 2, 1024);

    // attention (writes tripled hi/lo fp16 into a3)
    attn_mma<<<dim3(8, 128), 256, A_SMEM>>>(
        (const __half*)pq16, (const __half*)pk16, (const __half*)pv16t,
        (const float*)pb, a3);

    // output projection: hi/lo split, K=3072
    convert3<<<1024, 256>>>(Wo, w3, 1024, 1);
    gemm_tc<<<ggrid, 128, GEMM_SMEM>>>(a3, w3, bo, out, nullptr, 0, 3072);
}

// round 10
// speedup vs baseline: 5.9368x; 1.1472x over previous
#include <cuda_runtime.h>
#include <cuda_fp16.h>
#include <cstdint>
#include <math.h>

#define T_SEQ 1024
#define EMB   1024
#define NH    16
#define HD    64
#define BATCH 8
#define NREL  2047
#define K2    2048
#define NSTG  3

// ---------------- scratch (device globals) ----------------------------------
__device__ __align__(16) float g_bias[NREL * NH];      // [h][rel]
__device__ __align__(16) __half g_a3[25165824];        // QKV acts [3][8192,1024] / O2 [8192,2048]
__device__ __align__(16) __half g_w3[3145728];         // QKV W [3][1024,1024] / Wo2 [1024,2048]
__device__ __align__(16) __half g_q16[8388608];        // [bh][t][d]
__device__ __align__(16) __half g_k16[8388608];        // [bh][t][d]
__device__ __align__(16) __half g_v16t[8388608];       // [bh][d][t]

// ---------------- PTX helpers ------------------------------------------------
__device__ __forceinline__ uint32_t smem_u32(const void* p) {
    uint32_t a;
    asm("{ .reg .u64 t; cvta.to.shared.u64 t, %1; cvt.u32.u64 %0, t; }"
        : "=r"(a) : "l"(p));
    return a;
}

#define CP_ASYNC16(dst, src) \
    asm volatile("cp.async.cg.shared.global [%0], [%1], 16;" :: "r"(dst), "l"(src))
#define CP_COMMIT() asm volatile("cp.async.commit_group;" ::: "memory")
#define CP_WAIT1()  asm volatile("cp.async.wait_group 1;" ::: "memory")
#define CP_WAIT0()  asm volatile("cp.async.wait_group 0;" ::: "memory")

#define LDSM_X4(r0, r1, r2, r3, addr) \
    asm volatile("ldmatrix.sync.aligned.m8n8.x4.shared.b16 {%0,%1,%2,%3}, [%4];" \
        : "=r"(r0), "=r"(r1), "=r"(r2), "=r"(r3) : "r"(addr))

#define MMA16816(d, a0, a1, a2, a3, b0, b1) \
    asm volatile("mma.sync.aligned.m16n8k16.row.col.f32.f16.f16.f32 " \
        "{%0,%1,%2,%3},{%4,%5,%6,%7},{%8,%9},{%0,%1,%2,%3};" \
        : "+f"((d)[0]), "+f"((d)[1]), "+f"((d)[2]), "+f"((d)[3]) \
        : "r"(a0), "r"(a1), "r"(a2), "r"(a3), "r"(b0), "r"(b1))

__device__ __forceinline__ uint32_t pack_h2(float a, float b) {
    __half2 h = __float22half2_rn(make_float2(a, b));
    return *reinterpret_cast<uint32_t*>(&h);
}

// ---------------- kernel 1: bias interpolation -> [h][rel] ------------------
__global__ void bias_kernel(const float* __restrict__ table,
                            const float* __restrict__ offset,
                            float* __restrict__ out) {
    int idx = blockIdx.x * 256 + threadIdx.x;
    if (idx >= NREL * NH) return;
    int r = idx / NH, h = idx % NH;
    float bounded = tanhf(offset[0]) * 0.5f;
    float adj = fminf(fmaxf((float)r + bounded, 0.0f), 2046.0f);
    float lof = floorf(adj);
    int lo = (int)lof;
    int hi = (int)ceilf(adj);
    float w = adj - lof;
    out[h * NREL + r] = table[lo * NH + h] * (1.0f - w) + table[hi * NH + h] * w;
}

// ---------------- kernel 2a: plain fp32 -> fp16 (same layout) ----------------
__global__ void convert1(const float* __restrict__ in, __half* __restrict__ out,
                         int n4) {
    int idx = blockIdx.x * 256 + threadIdx.x;
    if (idx >= n4) return;
    float4 x = *(const float4*)&in[(size_t)idx * 4];
    __half2 p0 = __float22half2_rn(make_float2(x.x, x.y));
    __half2 p1 = __float22half2_rn(make_float2(x.z, x.w));
    __half2* dst = (__half2*)&out[(size_t)idx * 4];
    dst[0] = p0; dst[1] = p1;
}

// ---------------- kernel 2b: fp32 W [1024,1024] -> fp16 duplicated [1024,2048]
__global__ void convert_dup(const float* __restrict__ in, __half* __restrict__ out) {
    size_t idx = ((size_t)blockIdx.x * 256 + threadIdx.x) * 4;
    size_t row = idx >> 10;
    int col = (int)(idx & 1023);
    float4 x = *(const float4*)&in[idx];
    __half2 p0 = __float22half2_rn(make_float2(x.x, x.y));
    __half2 p1 = __float22half2_rn(make_float2(x.z, x.w));
    __half2* o0 = (__half2*)&out[row * K2 + col];
    __half2* o1 = (__half2*)&out[row * K2 + 1024 + col];
    o0[0] = p0; o0[1] = p1;
    o1[0] = p0; o1[1] = p1;
}

// ---------------- shared GEMM body: mma.sync fp16, 64x64 warp tiles ---------
// A [.,kdim], W [1024,kdim]; CTA 128x128, 4 warps. Epilogue modes:
//   0: fp32 row-major [8192,1024] + bias
//   1: fp16 [bh][t][d] + bias        2: fp16 [bh][d][t] + bias
#define ST_A   18432
#define ST_SZ  36864
__device__ __forceinline__ void gemm_body(
    const __half* __restrict__ gA, const __half* __restrict__ gB,
    const float* __restrict__ bias, float* __restrict__ outF,
    __half* __restrict__ outH, int mode, int kdim,
    size_t bm, size_t bn)
{
    extern __shared__ __align__(128) char smem[];
    uint32_t sbase = smem_u32(smem);

    int tid = threadIdx.x;
    int wid = tid >> 5, lid = tid & 31;
    int wm = wid >> 1, wn = wid & 1;
    int kch = kdim >> 6;

    int ldrow = tid >> 3;
    int ldch  = tid & 7;

    #pragma unroll
    for (int s = 0; s < NSTG - 1; s++) {
        uint32_t st = sbase + s * ST_SZ;
        #pragma unroll
        for (int i = 0; i < 8; i++) {
            int row = ldrow + i * 16;
            CP_ASYNC16(st + row * 144 + ldch * 16,
                       gA + (size_t)row * kdim + s * 64 + ldch * 8);
            CP_ASYNC16(st + ST_A + row * 144 + ldch * 16,
                       gB + (size_t)row * kdim + s * 64 + ldch * 8);
        }
        CP_COMMIT();
    }

    float acc[4][8][4];
    #pragma unroll
    for (int mi = 0; mi < 4; mi++)
        #pragma unroll
        for (int ni = 0; ni < 8; ni++)
            #pragma unroll
            for (int e = 0; e < 4; e++) acc[mi][ni][e] = 0.0f;

    uint32_t aOff = (uint32_t)((wm * 64 + (lid & 15)) * 144 + (lid >> 4) * 16);
    uint32_t bOff = (uint32_t)(ST_A +
        (wn * 64 + (lid & 7) + ((lid >> 4) << 3)) * 144 + ((lid >> 3) & 1) * 16);

    int cs = 0, ls = NSTG - 1;
    for (int c = 0; c < kch; c++) {
        CP_WAIT1();
        __syncthreads();

        if (c + NSTG - 1 < kch) {
            int cc = c + NSTG - 1;
            uint32_t st = sbase + ls * ST_SZ;
            #pragma unroll
            for (int i = 0; i < 8; i++) {
                int row = ldrow + i * 16;
                CP_ASYNC16(st + row * 144 + ldch * 16,
                           gA + (size_t)row * kdim + cc * 64 + ldch * 8);
                CP_ASYNC16(st + ST_A + row * 144 + ldch * 16,
                           gB + (size_t)row * kdim + cc * 64 + ldch * 8);
            }
        }
        CP_COMMIT();

        uint32_t st = sbase + cs * ST_SZ;
        #pragma unroll
        for (int kk = 0; kk < 4; kk++) {
            uint32_t a[4][4], b[4][4];
            #pragma unroll
            for (int mi = 0; mi < 4; mi++)
                LDSM_X4(a[mi][0], a[mi][1], a[mi][2], a[mi][3],
                        st + aOff + mi * (16 * 144) + kk * 32);
            #pragma unroll
            for (int nb = 0; nb < 4; nb++)
                LDSM_X4(b[nb][0], b[nb][1], b[nb][2], b[nb][3],
                        st + bOff + nb * (16 * 144) + kk * 32);
            #pragma unroll
            for (int mi = 0; mi < 4; mi++)
                #pragma unroll
                for (int nb = 0; nb < 4; nb++) {
                    MMA16816(acc[mi][nb * 2],
                             a[mi][0], a[mi][1], a[mi][2], a[mi][3],
                             b[nb][0], b[nb][1]);
                    MMA16816(acc[mi][nb * 2 + 1],
                             a[mi][0], a[mi][1], a[mi][2], a[mi][3],
                             b[nb][2], b[nb][3]);
                }
        }
        cs = (cs == NSTG - 1) ? 0 : cs + 1;
        ls = (ls == NSTG - 1) ? 0 : ls + 1;
    }

    #pragma unroll
    for (int mi = 0; mi < 4; mi++) {
        size_t r0 = bm + wm * 64 + mi * 16 + (lid >> 2);
        #pragma unroll
        for (int ni = 0; ni < 8; ni++) {
            size_t col = bn + wn * 64 + ni * 8 + (lid & 3) * 2;
            float2 bv = *(const float2*)&bias[col];
            float v00 = acc[mi][ni][0] + bv.x, v01 = acc[mi][ni][1] + bv.y;
            float v10 = acc[mi][ni][2] + bv.x, v11 = acc[mi][ni][3] + bv.y;
            if (mode == 0) {
                *(float2*)&outF[r0 * 1024 + col] = make_float2(v00, v01);
                *(float2*)&outF[(r0 + 8) * 1024 + col] = make_float2(v10, v11);
            } else if (mode == 1) {
                int h = (int)(col >> 6), d = (int)(col & 63);
                size_t b0 = r0 >> 10, t0 = r0 & 1023;
                __half2* d0 = (__half2*)&outH[(((b0 * NH + h) * T_SEQ + t0) * HD + d)];
                *d0 = __float22half2_rn(make_float2(v00, v01));
                size_t r1 = r0 + 8;
                __half2* d1 = (__half2*)&outH[(((r1 >> 10) * NH + h) * T_SEQ + (r1 & 1023)) * HD + d];
                *d1 = __float22half2_rn(make_float2(v10, v11));
            } else {
                int h = (int)(col >> 6), d = (int)(col & 63);
                size_t b0 = r0 >> 10, t0 = r0 & 1023;
                size_t base = ((b0 * NH + h) * HD + d) * T_SEQ;
                outH[base + t0] = __float2half_rn(v00);
                outH[base + T_SEQ + t0] = __float2half_rn(v01);
                outH[base + t0 + 8] = __float2half_rn(v10);
                outH[base + T_SEQ + t0 + 8] = __float2half_rn(v11);
            }
        }
    }
}

// ---------------- kernel 3a: batched Q/K/V projection (gridDim.z = 3) -------
__global__ void __launch_bounds__(128, 2)
gemm_qkv(const __half* __restrict__ Aall, const __half* __restrict__ Wall,
         const float* __restrict__ bq, const float* __restrict__ bk,
         const float* __restrict__ bv,
         __half* __restrict__ q16, __half* __restrict__ k16,
         __half* __restrict__ v16t)
{
    int z = blockIdx.z;
    const __half* A = Aall + (size_t)z * 8388608;
    const __half* W = Wall + (size_t)z * 1048576;
    const float* bias = (z == 0) ? bq : (z == 1) ? bk : bv;
    __half* outH = (z == 0) ? q16 : (z == 1) ? k16 : v16t;
    int mode = (z < 2) ? 1 : 2;
    size_t bm = (size_t)blockIdx.y * 128;
    size_t bn = (size_t)blockIdx.x * 128;
    gemm_body(A + bm * 1024, W + bn * 1024, bias, nullptr, outH, mode, 1024, bm, bn);
}

// ---------------- kernel 3b: output projection, K=2048 ----------------------
__global__ void __launch_bounds__(128, 2)
gemm_out(const __half* __restrict__ A, const __half* __restrict__ W,
         const float* __restrict__ bias, float* __restrict__ outF)
{
    size_t bm = (size_t)blockIdx.y * 128;
    size_t bn = (size_t)blockIdx.x * 128;
    gemm_body(A + bm * K2, W + bn * K2, bias, outF, nullptr, 0, K2, bm, bn);
}

// ---------------- kernel 4: fp16 mma flash attention -------------------------
#define A_SQ   0
#define A_SK   18432
#define A_SV   36864
#define A_SB   55296
#define A_SMEM 59904
__global__ void __launch_bounds__(256)
attn_mma(const __half* __restrict__ Q16, const __half* __restrict__ K16,
         const __half* __restrict__ V16t, const float* __restrict__ biasT,
         __half* __restrict__ Oa2)
{
    extern __shared__ __align__(128) char smem[];
    uint32_t sbase = smem_u32(smem);
    float* sbias = (float*)(smem + A_SB);

    int bh = blockIdx.y;
    int h = bh & (NH - 1), b = bh >> 4;
    int q0 = blockIdx.x * 128;
    int tid = threadIdx.x;
    int w = tid >> 5, lid = tid & 31;

    const __half* gQ = Q16 + ((size_t)bh * T_SEQ + q0) * HD;
    const __half* gK = K16 + (size_t)bh * T_SEQ * HD;
    const __half* gV = V16t + (size_t)bh * HD * T_SEQ;

    {
        #pragma unroll
        for (int i = 0; i < 4; i++) {
            int id = tid + i * 256;
            int row = id >> 3, ch = id & 7;
            CP_ASYNC16(sbase + A_SQ + row * 144 + ch * 16,
                       gQ + (size_t)row * HD + ch * 8);
        }
        #pragma unroll
        for (int i = 0; i < 2; i++) {
            int id = tid + i * 256;
            int row = id >> 3, ch = id & 7;
            CP_ASYNC16(sbase + A_SK + row * 144 + ch * 16,
                       gK + (size_t)row * HD + ch * 8);
            CP_ASYNC16(sbase + A_SV + row * 144 + ch * 16,
                       gV + (size_t)row * T_SEQ + ch * 8);
        }
        CP_COMMIT();
    }
    for (int j = tid; j < 1151; j += 256)
        sbias[j] = biasT[h * NREL + q0 + j];

    float o[8][4];
    #pragma unroll
    for (int i = 0; i < 8; i++)
        #pragma unroll
        for (int e = 0; e < 4; e++) o[i][e] = 0.0f;
    float m0 = -1e30f, m1 = -1e30f, l0 = 0.0f, l1 = 0.0f;
    uint32_t qa[4][4];

    int r0loc = w * 16 + (lid >> 2);

    for (int it = 0; it < 16; it++) {
        CP_WAIT0();
        __syncthreads();

        if (it < 15) {
            int kt2 = (it + 1) * 64;
            uint32_t bo = ((it + 1) & 1) * 9216;
            #pragma unroll
            for (int i = 0; i < 2; i++) {
                int id = tid + i * 256;
                int row = id >> 3, ch = id & 7;
                CP_ASYNC16(sbase + A_SK + bo + row * 144 + ch * 16,
                           gK + (size_t)(kt2 + row) * HD + ch * 8);
                CP_ASYNC16(sbase + A_SV + bo + row * 144 + ch * 16,
                           gV + (size_t)row * T_SEQ + kt2 + ch * 8);
            }
        }
        CP_COMMIT();

        if (it == 0) {
            #pragma unroll
            for (int kk = 0; kk < 4; kk++)
                LDSM_X4(qa[kk][0], qa[kk][1], qa[kk][2], qa[kk][3],
                        sbase + A_SQ + (w * 16 + (lid & 15)) * 144
                        + (lid >> 4) * 16 + kk * 32);
        }

        uint32_t kb = sbase + A_SK + (it & 1) * 9216;
        uint32_t vb = sbase + A_SV + (it & 1) * 9216;

        float s[8][4];
        #pragma unroll
        for (int i = 0; i < 8; i++)
            #pragma unroll
            for (int e = 0; e < 4; e++) s[i][e] = 0.0f;
        #pragma unroll
        for (int kk = 0; kk < 4; kk++) {
            #pragma unroll
            for (int nb = 0; nb < 4; nb++) {
                uint32_t bb[4];
                LDSM_X4(bb[0], bb[1], bb[2], bb[3],
                        kb + (nb * 16 + (lid & 7) + ((lid >> 4) << 3)) * 144
                        + ((lid >> 3) & 1) * 16 + kk * 32);
                MMA16816(s[nb * 2], qa[kk][0], qa[kk][1], qa[kk][2], qa[kk][3],
                         bb[0], bb[1]);
                MMA16816(s[nb * 2 + 1], qa[kk][0], qa[kk][1], qa[kk][2], qa[kk][3],
                         bb[2], bb[3]);
            }
        }

        int kcol = it * 64 + (lid & 3) * 2;
        #pragma unroll
        for (int nt = 0; nt < 8; nt++) {
            int jb = r0loc + 1023 - (kcol + nt * 8);
            s[nt][0] = s[nt][0] * 0.125f + sbias[jb];
            s[nt][1] = s[nt][1] * 0.125f + sbias[jb - 1];
            s[nt][2] = s[nt][2] * 0.125f + sbias[jb + 8];
            s[nt][3] = s[nt][3] * 0.125f + sbias[jb + 7];
        }

        float mx0 = -1e30f, mx1 = -1e30f;
        #pragma unroll
        for (int nt = 0; nt < 8; nt++) {
            mx0 = fmaxf(mx0, fmaxf(s[nt][0], s[nt][1]));
            mx1 = fmaxf(mx1, fmaxf(s[nt][2], s[nt][3]));
        }
        mx0 = fmaxf(mx0, __shfl_xor_sync(0xffffffffu, mx0, 1, 4));
        mx0 = fmaxf(mx0, __shfl_xor_sync(0xffffffffu, mx0, 2, 4));
        mx1 = fmaxf(mx1, __shfl_xor_sync(0xffffffffu, mx1, 1, 4));
        mx1 = fmaxf(mx1, __shfl_xor_sync(0xffffffffu, mx1, 2, 4));
        float mn0 = fmaxf(m0, mx0), mn1 = fmaxf(m1, mx1);
        float c0 = __expf(m0 - mn0), c1 = __expf(m1 - mn1);
        m0 = mn0; m1 = mn1;
        float ls0 = 0.0f, ls1 = 0.0f;
        #pragma unroll
        for (int nt = 0; nt < 8; nt++) {
            s[nt][0] = __expf(s[nt][0] - mn0); ls0 += s[nt][0];
            s[nt][1] = __expf(s[nt][1] - mn0); ls0 += s[nt][1];
            s[nt][2] = __expf(s[nt][2] - mn1); ls1 += s[nt][2];
            s[nt][3] = __expf(s[nt][3] - mn1); ls1 += s[nt][3];
        }
        l0 = l0 * c0 + ls0;
        l1 = l1 * c1 + ls1;
        #pragma unroll
        for (int dn = 0; dn < 8; dn++) {
            o[dn][0] *= c0; o[dn][1] *= c0;
            o[dn][2] *= c1; o[dn][3] *= c1;
        }

        uint32_t ap[4][4];
        #pragma unroll
        for (int kk = 0; kk < 4; kk++) {
            ap[kk][0] = pack_h2(s[2 * kk][0], s[2 * kk][1]);
            ap[kk][1] = pack_h2(s[2 * kk][2], s[2 * kk][3]);
            ap[kk][2] = pack_h2(s[2 * kk + 1][0], s[2 * kk + 1][1]);
            ap[kk][3] = pack_h2(s[2 * kk + 1][2], s[2 * kk + 1][3]);
        }

        #pragma unroll
        for (int kk = 0; kk < 4; kk++) {
            #pragma unroll
            for (int db = 0; db < 4; db++) {
                uint32_t bb[4];
                LDSM_X4(bb[0], bb[1], bb[2], bb[3],
                        vb + (db * 16 + (lid & 7) + ((lid >> 4) << 3)) * 144
                        + ((lid >> 3) & 1) * 16 + kk * 32);
                MMA16816(o[db * 2], ap[kk][0], ap[kk][1], ap[kk][2], ap[kk][3],
                         bb[0], bb[1]);
                MMA16816(o[db * 2 + 1], ap[kk][0], ap[kk][1], ap[kk][2], ap[kk][3],
                         bb[2], bb[3]);
            }
        }
    }

    // epilogue -> [O_hi | O_lo] fp16 into Oa2 [8192][2048]
    l0 += __shfl_xor_sync(0xffffffffu, l0, 1, 4);
    l0 += __shfl_xor_sync(0xffffffffu, l0, 2, 4);
    l1 += __shfl_xor_sync(0xffffffffu, l1, 1, 4);
    l1 += __shfl_xor_sync(0xffffffffu, l1, 2, 4);
    float inv0 = 1.0f / l0, inv1 = 1.0f / l1;
    size_t row0 = (size_t)b * T_SEQ + q0 + r0loc;
    #pragma unroll
    for (int idx = 0; idx < 8; idx++) {
        int d = (idx >> 1) * 16 + (idx & 1) * 8 + (lid & 3) * 2;
        int col = h * HD + d;
        float v00 = o[idx][0] * inv0, v01 = o[idx][1] * inv0;
        float v10 = o[idx][2] * inv1, v11 = o[idx][3] * inv1;
        __half h00 = __float2half_rn(v00), h01 = __float2half_rn(v01);
        __half h10 = __float2half_rn(v10), h11 = __float2half_rn(v11);
        __half2 hi0; hi0.x = h00; hi0.y = h01;
        __half2 hi1; hi1.x = h10; hi1.y = h11;
        __half2 lo0, lo1;
        lo0.x = __float2half_rn(v00 - __half2float(h00));
        lo0.y = __float2half_rn(v01 - __half2float(h01));
        lo1.x = __float2half_rn(v10 - __half2float(h10));
        lo1.y = __float2half_rn(v11 - __half2float(h11));
        size_t b0 = row0 * K2 + col;
        size_t b1 = (row0 + 8) * K2 + col;
        *(__half2*)&Oa2[b0] = hi0;
        *(__half2*)&Oa2[b0 + 1024] = lo0;
        *(__half2*)&Oa2[b1] = hi1;
        *(__half2*)&Oa2[b1 + 1024] = lo1;
    }
}

// ---------------- launch -----------------------------------------------------
extern "C" void kernel_launch(void* const* d_in, const int* in_sizes, int n_in,
                              void* d_out, int out_size) {
    const float* query = (const float*)d_in[0];
    const float* key_  = (const float*)d_in[1];
    const float* value = (const float*)d_in[2];
    const float* Wq = (const float*)d_in[3];
    const float* bq = (const float*)d_in[4];
    const float* Wk = (const float*)d_in[5];
    const float* bk = (const float*)d_in[6];
    const float* Wv = (const float*)d_in[7];
    const float* bv = (const float*)d_in[8];
    const float* Wo = (const float*)d_in[9];
    const float* bo = (const float*)d_in[10];
    const float* bias_table = (const float*)d_in[11];
    const float* offset     = (const float*)d_in[12];
    float* out = (float*)d_out;

    void *pb, *pa3, *pw3, *pq16, *pk16, *pv16t;
    cudaGetSymbolAddress(&pb, g_bias);
    cudaGetSymbolAddress(&pa3, g_a3);
    cudaGetSymbolAddress(&pw3, g_w3);
    cudaGetSymbolAddress(&pq16, g_q16);
    cudaGetSymbolAddress(&pk16, g_k16);
    cudaGetSymbolAddress(&pv16t, g_v16t);
    __half* a3 = (__half*)pa3;
    __half* w3 = (__half*)pw3;

    const int GEMM_SMEM = NSTG * ST_SZ;      // 110592
    cudaFuncSetAttribute(gemm_qkv, cudaFuncAttributeMaxDynamicSharedMemorySize, GEMM_SMEM);
    cudaFuncSetAttribute(gemm_out, cudaFuncAttributeMaxDynamicSharedMemorySize, GEMM_SMEM);
    cudaFuncSetAttribute(attn_mma, cudaFuncAttributeMaxDynamicSharedMemorySize, A_SMEM);

    bias_kernel<<<(NREL * NH + 255) / 256, 256>>>(bias_table, offset, (float*)pb);

    // converts: activations into a3 slots, weights into w3 slots
    convert1<<<8192, 256>>>(query, a3,                 8192 * 256);
    convert1<<<8192, 256>>>(key_,  a3 + 8388608,       8192 * 256);
    convert1<<<8192, 256>>>(value, a3 + 16777216,      8192 * 256);
    convert1<<<1024, 256>>>(Wq, w3,                    1024 * 256);
    convert1<<<1024, 256>>>(Wk, w3 + 1048576,          1024 * 256);
    convert1<<<1024, 256>>>(Wv, w3 + 2097152,          1024 * 256);

    // batched Q/K/V projection
    gemm_qkv<<<dim3(8, 64, 3), 128, GEMM_SMEM>>>(
        a3, w3, bq, bk, bv,
        (__half*)pq16, (__half*)pk16, (__half*)pv16t);

    // attention -> [O_hi | O_lo] into a3 (as [8192][2048])
    attn_mma<<<dim3(8, 128), 256, A_SMEM>>>(
        (const __half*)pq16, (const __half*)pk16, (const __half*)pv16t,
        (const float*)pb, a3);

    // output projection: A = [O_hi|O_lo], W = [Wo_hi|Wo_hi], K = 2048
    convert_dup<<<1024, 256>>>(Wo, w3);
    gemm_out<<<dim3(8, 64), 128, GEMM_SMEM>>>(a3, w3, bo, out);
}

// round 12
// speedup vs baseline: 7.0692x; 1.1907x over previous
#include <cuda_runtime.h>
#include <cuda_fp16.h>
#include <cstdint>
#include <math.h>

#define T_SEQ 1024
#define EMB   1024
#define NH    16
#define HD    64
#define BATCH 8
#define NREL  2047
#define NSTG  3

// ---------------- scratch (device globals) ----------------------------------
__device__ __align__(16) float g_bias[NREL * NH];      // [h][rel]
__device__ __align__(16) __half g_a3[25165824];        // QKV acts [3][8192,1024] / O [8192,1024]
__device__ __align__(16) __half g_w3[4194304];         // W slots [4][1024,1024] (q,k,v,o)
__device__ __align__(16) __half g_q16[8388608];        // [bh][t][d]
__device__ __align__(16) __half g_k16[8388608];        // [bh][t][d]
__device__ __align__(16) __half g_v16t[8388608];       // [bh][d][t]

// ---------------- PTX helpers ------------------------------------------------
__device__ __forceinline__ uint32_t smem_u32(const void* p) {
    uint32_t a;
    asm("{ .reg .u64 t; cvta.to.shared.u64 t, %1; cvt.u32.u64 %0, t; }"
        : "=r"(a) : "l"(p));
    return a;
}

#define CP_ASYNC16(dst, src) \
    asm volatile("cp.async.cg.shared.global [%0], [%1], 16;" :: "r"(dst), "l"(src))
#define CP_COMMIT() asm volatile("cp.async.commit_group;" ::: "memory")
#define CP_WAIT1()  asm volatile("cp.async.wait_group 1;" ::: "memory")
#define CP_WAIT0()  asm volatile("cp.async.wait_group 0;" ::: "memory")

#define LDSM_X4(r0, r1, r2, r3, addr) \
    asm volatile("ldmatrix.sync.aligned.m8n8.x4.shared.b16 {%0,%1,%2,%3}, [%4];" \
        : "=r"(r0), "=r"(r1), "=r"(r2), "=r"(r3) : "r"(addr))

#define MMA16816(d, a0, a1, a2, a3, b0, b1) \
    asm volatile("mma.sync.aligned.m16n8k16.row.col.f32.f16.f16.f32 " \
        "{%0,%1,%2,%3},{%4,%5,%6,%7},{%8,%9},{%0,%1,%2,%3};" \
        : "+f"((d)[0]), "+f"((d)[1]), "+f"((d)[2]), "+f"((d)[3]) \
        : "r"(a0), "r"(a1), "r"(a2), "r"(a3), "r"(b0), "r"(b1))

__device__ __forceinline__ uint32_t pack_h2(float a, float b) {
    __half2 h = __float22half2_rn(make_float2(a, b));
    return *reinterpret_cast<uint32_t*>(&h);
}

// ---------------- kernel 1: fused prep (converts + bias), 28800 blocks ------
// blocks [0,24576): activations q/k/v -> a3 slots (8192 each)
// blocks [24576,28672): weights Wq/Wk/Wv/Wo -> w3 slots (1024 each)
// blocks [28672,28800): bias interpolation (128 blocks)
__global__ void __launch_bounds__(256)
prep_kernel(const float* __restrict__ q, const float* __restrict__ k,
            const float* __restrict__ v,
            const float* __restrict__ Wq, const float* __restrict__ Wk,
            const float* __restrict__ Wv, const float* __restrict__ Wo,
            const float* __restrict__ table, const float* __restrict__ offset,
            __half* __restrict__ a3, __half* __restrict__ w3,
            float* __restrict__ biasOut)
{
    int blk = blockIdx.x;
    if (blk < 24576) {
        int slot = blk >> 13;                   // /8192
        const float* src = (slot == 0) ? q : (slot == 1) ? k : v;
        __half* dst = a3 + (size_t)slot * 8388608;
        size_t off = ((size_t)(blk & 8191) * 256 + threadIdx.x) * 4;
        float4 x = *(const float4*)&src[off];
        __half2 p0 = __float22half2_rn(make_float2(x.x, x.y));
        __half2 p1 = __float22half2_rn(make_float2(x.z, x.w));
        __half2* d = (__half2*)&dst[off];
        d[0] = p0; d[1] = p1;
    } else if (blk < 28672) {
        int wslot = (blk - 24576) >> 10;
        const float* src = (wslot == 0) ? Wq : (wslot == 1) ? Wk
                         : (wslot == 2) ? Wv : Wo;
        __half* dst = w3 + (size_t)wslot * 1048576;
        size_t off = ((size_t)((blk - 24576) & 1023) * 256 + threadIdx.x) * 4;
        float4 x = *(const float4*)&src[off];
        __half2 p0 = __float22half2_rn(make_float2(x.x, x.y));
        __half2 p1 = __float22half2_rn(make_float2(x.z, x.w));
        __half2* d = (__half2*)&dst[off];
        d[0] = p0; d[1] = p1;
    } else {
        int idx = (blk - 28672) * 256 + threadIdx.x;
        if (idx < NREL * NH) {
            int r = idx / NH, h = idx % NH;
            float bounded = tanhf(offset[0]) * 0.5f;
            float adj = fminf(fmaxf((float)r + bounded, 0.0f), 2046.0f);
            float lof = floorf(adj);
            int lo = (int)lof;
            int hi = (int)ceilf(adj);
            float w = adj - lof;
            biasOut[h * NREL + r] =
                table[lo * NH + h] * (1.0f - w) + table[hi * NH + h] * w;
        }
    }
}

// ---------------- shared GEMM body: mma.sync fp16, 64x64 warp tiles ---------
#define ST_A   18432
#define ST_SZ  36864
__device__ __forceinline__ void gemm_body(
    const __half* __restrict__ gA, const __half* __restrict__ gB,
    const float* __restrict__ bias, float* __restrict__ outF,
    __half* __restrict__ outH, int mode, int kdim,
    size_t bm, size_t bn)
{
    extern __shared__ __align__(128) char smem[];
    uint32_t sbase = smem_u32(smem);

    int tid = threadIdx.x;
    int wid = tid >> 5, lid = tid & 31;
    int wm = wid >> 1, wn = wid & 1;
    int kch = kdim >> 6;

    int ldrow = tid >> 3;
    int ldch  = tid & 7;

    #pragma unroll
    for (int s = 0; s < NSTG - 1; s++) {
        uint32_t st = sbase + s * ST_SZ;
        #pragma unroll
        for (int i = 0; i < 8; i++) {
            int row = ldrow + i * 16;
            CP_ASYNC16(st + row * 144 + ldch * 16,
                       gA + (size_t)row * kdim + s * 64 + ldch * 8);
            CP_ASYNC16(st + ST_A + row * 144 + ldch * 16,
                       gB + (size_t)row * kdim + s * 64 + ldch * 8);
        }
        CP_COMMIT();
    }

    float acc[4][8][4];
    #pragma unroll
    for (int mi = 0; mi < 4; mi++)
        #pragma unroll
        for (int ni = 0; ni < 8; ni++)
            #pragma unroll
            for (int e = 0; e < 4; e++) acc[mi][ni][e] = 0.0f;

    uint32_t aOff = (uint32_t)((wm * 64 + (lid & 15)) * 144 + (lid >> 4) * 16);
    uint32_t bOff = (uint32_t)(ST_A +
        (wn * 64 + (lid & 7) + ((lid >> 4) << 3)) * 144 + ((lid >> 3) & 1) * 16);

    int cs = 0, ls = NSTG - 1;
    for (int c = 0; c < kch; c++) {
        CP_WAIT1();
        __syncthreads();

        if (c + NSTG - 1 < kch) {
            int cc = c + NSTG - 1;
            uint32_t st = sbase + ls * ST_SZ;
            #pragma unroll
            for (int i = 0; i < 8; i++) {
                int row = ldrow + i * 16;
                CP_ASYNC16(st + row * 144 + ldch * 16,
                           gA + (size_t)row * kdim + cc * 64 + ldch * 8);
                CP_ASYNC16(st + ST_A + row * 144 + ldch * 16,
                           gB + (size_t)row * kdim + cc * 64 + ldch * 8);
            }
        }
        CP_COMMIT();

        uint32_t st = sbase + cs * ST_SZ;
        #pragma unroll
        for (int kk = 0; kk < 4; kk++) {
            uint32_t a[4][4], b[4][4];
            #pragma unroll
            for (int mi = 0; mi < 4; mi++)
                LDSM_X4(a[mi][0], a[mi][1], a[mi][2], a[mi][3],
                        st + aOff + mi * (16 * 144) + kk * 32);
            #pragma unroll
            for (int nb = 0; nb < 4; nb++)
                LDSM_X4(b[nb][0], b[nb][1], b[nb][2], b[nb][3],
                        st + bOff + nb * (16 * 144) + kk * 32);
            #pragma unroll
            for (int mi = 0; mi < 4; mi++)
                #pragma unroll
                for (int nb = 0; nb < 4; nb++) {
                    MMA16816(acc[mi][nb * 2],
                             a[mi][0], a[mi][1], a[mi][2], a[mi][3],
                             b[nb][0], b[nb][1]);
                    MMA16816(acc[mi][nb * 2 + 1],
                             a[mi][0], a[mi][1], a[mi][2], a[mi][3],
                             b[nb][2], b[nb][3]);
                }
        }
        cs = (cs == NSTG - 1) ? 0 : cs + 1;
        ls = (ls == NSTG - 1) ? 0 : ls + 1;
    }

    #pragma unroll
    for (int mi = 0; mi < 4; mi++) {
        size_t r0 = bm + wm * 64 + mi * 16 + (lid >> 2);
        #pragma unroll
        for (int ni = 0; ni < 8; ni++) {
            size_t col = bn + wn * 64 + ni * 8 + (lid & 3) * 2;
            float2 bv = *(const float2*)&bias[col];
            float v00 = acc[mi][ni][0] + bv.x, v01 = acc[mi][ni][1] + bv.y;
            float v10 = acc[mi][ni][2] + bv.x, v11 = acc[mi][ni][3] + bv.y;
            if (mode == 0) {
                *(float2*)&outF[r0 * 1024 + col] = make_float2(v00, v01);
                *(float2*)&outF[(r0 + 8) * 1024 + col] = make_float2(v10, v11);
            } else if (mode == 1) {
                int h = (int)(col >> 6), d = (int)(col & 63);
                size_t b0 = r0 >> 10, t0 = r0 & 1023;
                __half2* d0 = (__half2*)&outH[(((b0 * NH + h) * T_SEQ + t0) * HD + d)];
                *d0 = __float22half2_rn(make_float2(v00, v01));
                size_t r1 = r0 + 8;
                __half2* d1 = (__half2*)&outH[(((r1 >> 10) * NH + h) * T_SEQ + (r1 & 1023)) * HD + d];
                *d1 = __float22half2_rn(make_float2(v10, v11));
            } else {
                int h = (int)(col >> 6), d = (int)(col & 63);
                size_t b0 = r0 >> 10, t0 = r0 & 1023;
                size_t base = ((b0 * NH + h) * HD + d) * T_SEQ;
                outH[base + t0] = __float2half_rn(v00);
                outH[base + T_SEQ + t0] = __float2half_rn(v01);
                outH[base + t0 + 8] = __float2half_rn(v10);
                outH[base + T_SEQ + t0 + 8] = __float2half_rn(v11);
            }
        }
    }
}

// ---------------- kernel 2a: batched Q/K/V projection (gridDim.z = 3) -------
__global__ void __launch_bounds__(128, 2)
gemm_qkv(const __half* __restrict__ Aall, const __half* __restrict__ Wall,
         const float* __restrict__ bq, const float* __restrict__ bk,
         const float* __restrict__ bv,
         __half* __restrict__ q16, __half* __restrict__ k16,
         __half* __restrict__ v16t)
{
    int z = blockIdx.z;
    const __half* A = Aall + (size_t)z * 8388608;
    const __half* W = Wall + (size_t)z * 1048576;
    const float* bias = (z == 0) ? bq : (z == 1) ? bk : bv;
    __half* outH = (z == 0) ? q16 : (z == 1) ? k16 : v16t;
    int mode = (z < 2) ? 1 : 2;
    size_t bm = (size_t)blockIdx.y * 128;
    size_t bn = (size_t)blockIdx.x * 128;
    gemm_body(A + bm * 1024, W + bn * 1024, bias, nullptr, outH, mode, 1024, bm, bn);
}

// ---------------- kernel 2b: output projection, K=1024 ----------------------
__global__ void __launch_bounds__(128, 2)
gemm_out(const __half* __restrict__ A, const __half* __restrict__ W,
         const float* __restrict__ bias, float* __restrict__ outF)
{
    size_t bm = (size_t)blockIdx.y * 128;
    size_t bn = (size_t)blockIdx.x * 128;
    gemm_body(A + bm * 1024, W + bn * 1024, bias, outF, nullptr, 0, 1024, bm, bn);
}

// ---------------- kernel 3: fp16 mma flash attention -------------------------
#define A_SQ   0
#define A_SK   18432
#define A_SV   36864
#define A_SB   55296
#define A_SMEM 59904
__global__ void __launch_bounds__(256)
attn_mma(const __half* __restrict__ Q16, const __half* __restrict__ K16,
         const __half* __restrict__ V16t, const float* __restrict__ biasT,
         __half* __restrict__ Oh)
{
    extern __shared__ __align__(128) char smem[];
    uint32_t sbase = smem_u32(smem);
    float* sbias = (float*)(smem + A_SB);

    int bh = blockIdx.y;
    int h = bh & (NH - 1), b = bh >> 4;
    int q0 = blockIdx.x * 128;
    int tid = threadIdx.x;
    int w = tid >> 5, lid = tid & 31;

    const __half* gQ = Q16 + ((size_t)bh * T_SEQ + q0) * HD;
    const __half* gK = K16 + (size_t)bh * T_SEQ * HD;
    const __half* gV = V16t + (size_t)bh * HD * T_SEQ;

    {
        #pragma unroll
        for (int i = 0; i < 4; i++) {
            int id = tid + i * 256;
            int row = id >> 3, ch = id & 7;
            CP_ASYNC16(sbase + A_SQ + row * 144 + ch * 16,
                       gQ + (size_t)row * HD + ch * 8);
        }
        #pragma unroll
        for (int i = 0; i < 2; i++) {
            int id = tid + i * 256;
            int row = id >> 3, ch = id & 7;
            CP_ASYNC16(sbase + A_SK + row * 144 + ch * 16,
                       gK + (size_t)row * HD + ch * 8);
            CP_ASYNC16(sbase + A_SV + row * 144 + ch * 16,
                       gV + (size_t)row * T_SEQ + ch * 8);
        }
        CP_COMMIT();
    }
    for (int j = tid; j < 1151; j += 256)
        sbias[j] = biasT[h * NREL + q0 + j];

    float o[8][4];
    #pragma unroll
    for (int i = 0; i < 8; i++)
        #pragma unroll
        for (int e = 0; e < 4; e++) o[i][e] = 0.0f;
    float m0 = -1e30f, m1 = -1e30f, l0 = 0.0f, l1 = 0.0f;
    uint32_t qa[4][4];

    int r0loc = w * 16 + (lid >> 2);

    for (int it = 0; it < 16; it++) {
        CP_WAIT0();
        __syncthreads();

        if (it < 15) {
            int kt2 = (it + 1) * 64;
            uint32_t bo = ((it + 1) & 1) * 9216;
            #pragma unroll
            for (int i = 0; i < 2; i++) {
                int id = tid + i * 256;
                int row = id >> 3, ch = id & 7;
                CP_ASYNC16(sbase + A_SK + bo + row * 144 + ch * 16,
                           gK + (size_t)(kt2 + row) * HD + ch * 8);
                CP_ASYNC16(sbase + A_SV + bo + row * 144 + ch * 16,
                           gV + (size_t)row * T_SEQ + kt2 + ch * 8);
            }
        }
        CP_COMMIT();

        if (it == 0) {
            #pragma unroll
            for (int kk = 0; kk < 4; kk++)
                LDSM_X4(qa[kk][0], qa[kk][1], qa[kk][2], qa[kk][3],
                        sbase + A_SQ + (w * 16 + (lid & 15)) * 144
                        + (lid >> 4) * 16 + kk * 32);
        }

        uint32_t kb = sbase + A_SK + (it & 1) * 9216;
        uint32_t vb = sbase + A_SV + (it & 1) * 9216;

        float s[8][4];
        #pragma unroll
        for (int i = 0; i < 8; i++)
            #pragma unroll
            for (int e = 0; e < 4; e++) s[i][e] = 0.0f;
        #pragma unroll
        for (int kk = 0; kk < 4; kk++) {
            #pragma unroll
            for (int nb = 0; nb < 4; nb++) {
                uint32_t bb[4];
                LDSM_X4(bb[0], bb[1], bb[2], bb[3],
                        kb + (nb * 16 + (lid & 7) + ((lid >> 4) << 3)) * 144
                        + ((lid >> 3) & 1) * 16 + kk * 32);
                MMA16816(s[nb * 2], qa[kk][0], qa[kk][1], qa[kk][2], qa[kk][3],
                         bb[0], bb[1]);
                MMA16816(s[nb * 2 + 1], qa[kk][0], qa[kk][1], qa[kk][2], qa[kk][3],
                         bb[2], bb[3]);
            }
        }

        int kcol = it * 64 + (lid & 3) * 2;
        #pragma unroll
        for (int nt = 0; nt < 8; nt++) {
            int jb = r0loc + 1023 - (kcol + nt * 8);
            s[nt][0] = s[nt][0] * 0.125f + sbias[jb];
            s[nt][1] = s[nt][1] * 0.125f + sbias[jb - 1];
            s[nt][2] = s[nt][2] * 0.125f + sbias[jb + 8];
            s[nt][3] = s[nt][3] * 0.125f + sbias[jb + 7];
        }

        float mx0 = -1e30f, mx1 = -1e30f;
        #pragma unroll
        for (int nt = 0; nt < 8; nt++) {
            mx0 = fmaxf(mx0, fmaxf(s[nt][0], s[nt][1]));
            mx1 = fmaxf(mx1, fmaxf(s[nt][2], s[nt][3]));
        }
        mx0 = fmaxf(mx0, __shfl_xor_sync(0xffffffffu, mx0, 1, 4));
        mx0 = fmaxf(mx0, __shfl_xor_sync(0xffffffffu, mx0, 2, 4));
        mx1 = fmaxf(mx1, __shfl_xor_sync(0xffffffffu, mx1, 1, 4));
        mx1 = fmaxf(mx1, __shfl_xor_sync(0xffffffffu, mx1, 2, 4));
        float mn0 = fmaxf(m0, mx0), mn1 = fmaxf(m1, mx1);
        float c0 = __expf(m0 - mn0), c1 = __expf(m1 - mn1);
        m0 = mn0; m1 = mn1;
        float ls0 = 0.0f, ls1 = 0.0f;
        #pragma unroll
        for (int nt = 0; nt < 8; nt++) {
            s[nt][0] = __expf(s[nt][0] - mn0); ls0 += s[nt][0];
            s[nt][1] = __expf(s[nt][1] - mn0); ls0 += s[nt][1];
            s[nt][2] = __expf(s[nt][2] - mn1); ls1 += s[nt][2];
            s[nt][3] = __expf(s[nt][3] - mn1); ls1 += s[nt][3];
        }
        l0 = l0 * c0 + ls0;
        l1 = l1 * c1 + ls1;
        #pragma unroll
        for (int dn = 0; dn < 8; dn++) {
            o[dn][0] *= c0; o[dn][1] *= c0;
            o[dn][2] *= c1; o[dn][3] *= c1;
        }

        uint32_t ap[4][4];
        #pragma unroll
        for (int kk = 0; kk < 4; kk++) {
            ap[kk][0] = pack_h2(s[2 * kk][0], s[2 * kk][1]);
            ap[kk][1] = pack_h2(s[2 * kk][2], s[2 * kk][3]);
            ap[kk][2] = pack_h2(s[2 * kk + 1][0], s[2 * kk + 1][1]);
            ap[kk][3] = pack_h2(s[2 * kk + 1][2], s[2 * kk + 1][3]);
        }

        #pragma unroll
        for (int kk = 0; kk < 4; kk++) {
            #pragma unroll
            for (int db = 0; db < 4; db++) {
                uint32_t bb[4];
                LDSM_X4(bb[0], bb[1], bb[2], bb[3],
                        vb + (db * 16 + (lid & 7) + ((lid >> 4) << 3)) * 144
                        + ((lid >> 3) & 1) * 16 + kk * 32);
                MMA16816(o[db * 2], ap[kk][0], ap[kk][1], ap[kk][2], ap[kk][3],
                         bb[0], bb[1]);
                MMA16816(o[db * 2 + 1], ap[kk][0], ap[kk][1], ap[kk][2], ap[kk][3],
                         bb[2], bb[3]);
            }
        }
    }

    // epilogue -> fp16 O [8192][1024]
    l0 += __shfl_xor_sync(0xffffffffu, l0, 1, 4);
    l0 += __shfl_xor_sync(0xffffffffu, l0, 2, 4);
    l1 += __shfl_xor_sync(0xffffffffu, l1, 1, 4);
    l1 += __shfl_xor_sync(0xffffffffu, l1, 2, 4);
    float inv0 = 1.0f / l0, inv1 = 1.0f / l1;
    size_t row0 = (size_t)b * T_SEQ + q0 + r0loc;
    #pragma unroll
    for (int idx = 0; idx < 8; idx++) {
        int d = (idx >> 1) * 16 + (idx & 1) * 8 + (lid & 3) * 2;
        int col = h * HD + d;
        *(__half2*)&Oh[row0 * 1024 + col] =
            __float22half2_rn(make_float2(o[idx][0] * inv0, o[idx][1] * inv0));
        *(__half2*)&Oh[(row0 + 8) * 1024 + col] =
            __float22half2_rn(make_float2(o[idx][2] * inv1, o[idx][3] * inv1));
    }
}

// ---------------- launch -----------------------------------------------------
extern "C" void kernel_launch(void* const* d_in, const int* in_sizes, int n_in,
                              void* d_out, int out_size) {
    const float* query = (const float*)d_in[0];
    const float* key_  = (const float*)d_in[1];
    const float* value = (const float*)d_in[2];
    const float* Wq = (const float*)d_in[3];
    const float* bq = (const float*)d_in[4];
    const float* Wk = (const float*)d_in[5];
    const float* bk = (const float*)d_in[6];
    const float* Wv = (const float*)d_in[7];
    const float* bv = (const float*)d_in[8];
    const float* Wo = (const float*)d_in[9];
    const float* bo = (const float*)d_in[10];
    const float* bias_table = (const float*)d_in[11];
    const float* offset     = (const float*)d_in[12];
    float* out = (float*)d_out;

    void *pb, *pa3, *pw3, *pq16, *pk16, *pv16t;
    cudaGetSymbolAddress(&pb, g_bias);
    cudaGetSymbolAddress(&pa3, g_a3);
    cudaGetSymbolAddress(&pw3, g_w3);
    cudaGetSymbolAddress(&pq16, g_q16);
    cudaGetSymbolAddress(&pk16, g_k16);
    cudaGetSymbolAddress(&pv16t, g_v16t);
    __half* a3 = (__half*)pa3;
    __half* w3 = (__half*)pw3;

    const int GEMM_SMEM = NSTG * ST_SZ;      // 110592
    cudaFuncSetAttribute(gemm_qkv, cudaFuncAttributeMaxDynamicSharedMemorySize, GEMM_SMEM);
    cudaFuncSetAttribute(gemm_out, cudaFuncAttributeMaxDynamicSharedMemorySize, GEMM_SMEM);
    cudaFuncSetAttribute(attn_mma, cudaFuncAttributeMaxDynamicSharedMemorySize, A_SMEM);

    // one fused prep: all converts + bias
    prep_kernel<<<28800, 256>>>(query, key_, value, Wq, Wk, Wv, Wo,
                                bias_table, offset, a3, w3, (float*)pb);

    // batched Q/K/V projection
    gemm_qkv<<<dim3(8, 64, 3), 128, GEMM_SMEM>>>(
        a3, w3, bq, bk, bv,
        (__half*)pq16, (__half*)pk16, (__half*)pv16t);

    // attention -> fp16 O into a3 (as [8192][1024])
    attn_mma<<<dim3(8, 128), 256, A_SMEM>>>(
        (const __half*)pq16, (const __half*)pk16, (const __half*)pv16t,
        (const float*)pb, a3);

    // output projection: O_hi * Wo_hi, K = 1024
    gemm_out<<<dim3(8, 64), 128, GEMM_SMEM>>>(a3, w3 + 3145728, bo, out);
}